// round 1
// baseline (speedup 1.0000x reference)
#include <cuda_runtime.h>
#include <cuda_bf16.h>
#include <cstddef>

// Problem constants
#define BATCH   4
#define S_LEN   2048
#define DMODEL  1024
#define NH      16
#define DH      64
#define NT      (BATCH * S_LEN)     // 8192 rows
#define QKV_N   (3 * DMODEL)        // 3072

// Scratch (device globals: allocation-free)
__device__ float g_qkv[(size_t)NT * QKV_N];    // [8192, 3072]
__device__ float g_attn[(size_t)NT * DMODEL];  // [8192, 1024] merged-heads attention output

// ---------------------------------------------------------------------------
// SGEMM with bias: C[M,N] = A[M,K] @ B[K,N] + bias[N]
// 128x128 block, BK=8, 256 threads, 8x8 per thread. Assumes M%128==0,
// N%128==0, K%8==0 (true for all calls here).
// ---------------------------------------------------------------------------
__global__ __launch_bounds__(256) void sgemm_bias_kernel(
    const float* __restrict__ A, const float* __restrict__ B,
    const float* __restrict__ bias, float* __restrict__ C,
    int M, int N, int K)
{
    const int BM = 128, BN = 128, BK = 8;
    __shared__ float As[BK][BM];
    __shared__ float Bs[BK][BN];

    const int tid = threadIdx.x;
    const int bx = blockIdx.x;   // tile along N
    const int by = blockIdx.y;   // tile along M

    const float* Ab = A + (size_t)by * BM * K;
    const float* Bb = B + (size_t)bx * BN;

    const int aRow = tid >> 1;            // 0..127
    const int aCol = (tid & 1) * 4;       // 0 or 4
    const int bRow = tid >> 5;            // 0..7
    const int bCol = (tid & 31) * 4;      // 0..124

    const int ty = tid >> 4;              // 0..15
    const int tx = tid & 15;              // 0..15

    float acc[8][8];
    #pragma unroll
    for (int i = 0; i < 8; i++)
        #pragma unroll
        for (int j = 0; j < 8; j++) acc[i][j] = 0.0f;

    for (int k0 = 0; k0 < K; k0 += BK) {
        float4 av = *(const float4*)(Ab + (size_t)aRow * K + k0 + aCol);
        float4 bv = *(const float4*)(Bb + (size_t)(k0 + bRow) * N + bCol);
        As[aCol + 0][aRow] = av.x;
        As[aCol + 1][aRow] = av.y;
        As[aCol + 2][aRow] = av.z;
        As[aCol + 3][aRow] = av.w;
        *(float4*)&Bs[bRow][bCol] = bv;
        __syncthreads();

        #pragma unroll
        for (int k = 0; k < BK; k++) {
            float ra[8], rb[8];
            *(float4*)&ra[0] = *(const float4*)&As[k][ty * 8];
            *(float4*)&ra[4] = *(const float4*)&As[k][ty * 8 + 4];
            *(float4*)&rb[0] = *(const float4*)&Bs[k][tx * 8];
            *(float4*)&rb[4] = *(const float4*)&Bs[k][tx * 8 + 4];
            #pragma unroll
            for (int i = 0; i < 8; i++)
                #pragma unroll
                for (int j = 0; j < 8; j++)
                    acc[i][j] += ra[i] * rb[j];
        }
        __syncthreads();
    }

    const int rowBase = by * BM + ty * 8;
    const int colBase = bx * BN + tx * 8;
    float b0 = bias[colBase + 0], b1 = bias[colBase + 1];
    float b2 = bias[colBase + 2], b3 = bias[colBase + 3];
    float b4 = bias[colBase + 4], b5 = bias[colBase + 5];
    float b6 = bias[colBase + 6], b7 = bias[colBase + 7];
    #pragma unroll
    for (int i = 0; i < 8; i++) {
        float* crow = C + (size_t)(rowBase + i) * N + colBase;
        *(float4*)(crow + 0) = make_float4(acc[i][0] + b0, acc[i][1] + b1,
                                           acc[i][2] + b2, acc[i][3] + b3);
        *(float4*)(crow + 4) = make_float4(acc[i][4] + b4, acc[i][5] + b5,
                                           acc[i][6] + b6, acc[i][7] + b7);
    }
}

// ---------------------------------------------------------------------------
// Flash attention (fp32, causal). One block = one (b, h, 64-row q tile).
// Online softmax over 64-key tiles; skips fully-masked tiles.
// qkv layout: [NT, 3072], q at col h*64, k at 1024 + h*64, v at 2048 + h*64.
// Output: merged heads [NT, 1024], head h in cols h*64..h*64+63.
// ---------------------------------------------------------------------------
#define TLDS 65   // padded smem row stride

__global__ __launch_bounds__(256) void flash_attn_kernel(
    const float* __restrict__ qkv, float* __restrict__ outp)
{
    extern __shared__ float sm[];
    float* Qs = sm;                 // [64][65]
    float* Ks = Qs + 64 * TLDS;     // [64][65]
    float* Vs = Ks + 64 * TLDS;     // [64][65]
    float* Ps = Vs + 64 * TLDS;     // [64][65]

    const int qt = blockIdx.x;       // 0..31
    const int h  = blockIdx.y;       // 0..15
    const int b  = blockIdx.z;       // 0..3

    const int tid = threadIdx.x;
    const int tx = tid & 15;         // key-column group
    const int ty = tid >> 4;         // query-row group

    const int q0 = qt * 64;
    const float scale = 0.125f;      // 1/sqrt(64)

    const float* qbase = qkv + (size_t)b * S_LEN * QKV_N + h * DH;
    const float* kbase = qbase + DMODEL;
    const float* vbase = qbase + 2 * DMODEL;

    // Load Q tile (pre-scaled)
    for (int i = tid; i < 64 * 64; i += 256) {
        int r = i >> 6, d = i & 63;
        Qs[r * TLDS + d] = qbase[(size_t)(q0 + r) * QKV_N + d] * scale;
    }

    float m[4], l[4], acc[4][4];
    #pragma unroll
    for (int i = 0; i < 4; i++) {
        m[i] = -1e30f; l[i] = 0.0f;
        #pragma unroll
        for (int j = 0; j < 4; j++) acc[i][j] = 0.0f;
    }

    for (int kt = 0; kt <= qt; ++kt) {
        __syncthreads();   // protects Qs (first iter) / Ks,Vs,Ps reuse
        const int k0 = kt * 64;
        for (int i = tid; i < 64 * 64; i += 256) {
            int r = i >> 6, d = i & 63;
            Ks[r * TLDS + d] = kbase[(size_t)(k0 + r) * QKV_N + d];
            Vs[r * TLDS + d] = vbase[(size_t)(k0 + r) * QKV_N + d];
        }
        __syncthreads();

        // S = Q @ K^T (scaled)
        float s[4][4];
        #pragma unroll
        for (int i = 0; i < 4; i++)
            #pragma unroll
            for (int j = 0; j < 4; j++) s[i][j] = 0.0f;

        #pragma unroll 4
        for (int d = 0; d < 64; d++) {
            float qv[4], kv[4];
            #pragma unroll
            for (int i = 0; i < 4; i++) qv[i] = Qs[(ty * 4 + i) * TLDS + d];
            #pragma unroll
            for (int j = 0; j < 4; j++) kv[j] = Ks[(tx * 4 + j) * TLDS + d];
            #pragma unroll
            for (int i = 0; i < 4; i++)
                #pragma unroll
                for (int j = 0; j < 4; j++)
                    s[i][j] += qv[i] * kv[j];
        }

        if (kt == qt) {
            #pragma unroll
            for (int i = 0; i < 4; i++)
                #pragma unroll
                for (int j = 0; j < 4; j++)
                    if (tx * 4 + j > ty * 4 + i) s[i][j] = -1e30f;
        }

        // Online softmax update (per query row; 16 lanes share a row group)
        #pragma unroll
        for (int i = 0; i < 4; i++) {
            float rm = fmaxf(fmaxf(s[i][0], s[i][1]), fmaxf(s[i][2], s[i][3]));
            #pragma unroll
            for (int o = 8; o >= 1; o >>= 1)
                rm = fmaxf(rm, __shfl_xor_sync(0xffffffffu, rm, o, 16));
            float mn = fmaxf(m[i], rm);
            float alpha = __expf(m[i] - mn);
            m[i] = mn;
            float rs = 0.0f;
            #pragma unroll
            for (int j = 0; j < 4; j++) {
                s[i][j] = __expf(s[i][j] - mn);
                rs += s[i][j];
            }
            #pragma unroll
            for (int o = 8; o >= 1; o >>= 1)
                rs += __shfl_xor_sync(0xffffffffu, rs, o, 16);
            l[i] = l[i] * alpha + rs;
            #pragma unroll
            for (int j = 0; j < 4; j++) acc[i][j] *= alpha;
        }

        // Store P, then O += P @ V
        #pragma unroll
        for (int i = 0; i < 4; i++)
            #pragma unroll
            for (int j = 0; j < 4; j++)
                Ps[(ty * 4 + i) * TLDS + tx * 4 + j] = s[i][j];
        __syncthreads();

        #pragma unroll 4
        for (int k = 0; k < 64; k++) {
            float pv[4], vv[4];
            #pragma unroll
            for (int i = 0; i < 4; i++) pv[i] = Ps[(ty * 4 + i) * TLDS + k];
            #pragma unroll
            for (int j = 0; j < 4; j++) vv[j] = Vs[k * TLDS + tx * 4 + j];
            #pragma unroll
            for (int i = 0; i < 4; i++)
                #pragma unroll
                for (int j = 0; j < 4; j++)
                    acc[i][j] += pv[i] * vv[j];
        }
    }

    // Normalize and write merged-heads output
    #pragma unroll
    for (int i = 0; i < 4; i++) {
        float inv = 1.0f / l[i];
        int row = q0 + ty * 4 + i;
        float* orow = outp + ((size_t)b * S_LEN + row) * DMODEL + h * DH + tx * 4;
        #pragma unroll
        for (int j = 0; j < 4; j++) orow[j] = acc[i][j] * inv;
    }
}

// ---------------------------------------------------------------------------
// Launch
// ---------------------------------------------------------------------------
extern "C" void kernel_launch(void* const* d_in, const int* in_sizes, int n_in,
                              void* d_out, int out_size)
{
    const float* hidden  = (const float*)d_in[0];   // [4,2048,1024]
    const float* w_attn  = (const float*)d_in[1];   // [1024,3072]
    const float* b_attn  = (const float*)d_in[2];   // [3072]
    const float* w_proj  = (const float*)d_in[3];   // [1024,1024]
    const float* b_proj  = (const float*)d_in[4];   // [1024]
    float* out = (float*)d_out;                     // [4,2048,1024]

    float *qkv, *attn;
    cudaGetSymbolAddress((void**)&qkv, g_qkv);
    cudaGetSymbolAddress((void**)&attn, g_attn);

    // 1) QKV projection: [8192,1024] @ [1024,3072] + bias
    {
        dim3 grid(QKV_N / 128, NT / 128);
        sgemm_bias_kernel<<<grid, 256>>>(hidden, w_attn, b_attn, qkv,
                                         NT, QKV_N, DMODEL);
    }

    // 2) Causal flash attention per (b, h, q-tile)
    {
        size_t smem = (size_t)4 * 64 * TLDS * sizeof(float);  // 66560 B
        cudaFuncSetAttribute(flash_attn_kernel,
                             cudaFuncAttributeMaxDynamicSharedMemorySize,
                             (int)smem);
        dim3 grid(S_LEN / 64, NH, BATCH);
        flash_attn_kernel<<<grid, 256, smem>>>(qkv, attn);
    }

    // 3) Output projection: [8192,1024] @ [1024,1024] + bias
    {
        dim3 grid(DMODEL / 128, NT / 128);
        sgemm_bias_kernel<<<grid, 256>>>(attn, w_proj, b_proj, out,
                                         NT, DMODEL, DMODEL);
    }
}

// round 3
// speedup vs baseline: 1.5453x; 1.5453x over previous
#include <cuda_runtime.h>
#include <cuda_bf16.h>
#include <cstdint>
#include <cstddef>

// Problem constants
#define BATCH   4
#define S_LEN   2048
#define DMODEL  1024
#define NH      16
#define DH      64
#define NT      (BATCH * S_LEN)     // 8192 rows
#define QKV_N   (3 * DMODEL)        // 3072
#define KDIM    1024

// Scratch (device globals: allocation-free)
__device__ float g_qkv[(size_t)NT * QKV_N];    // [8192, 3072]
__device__ float g_attn[(size_t)NT * DMODEL];  // [8192, 1024]

__device__ __forceinline__ uint32_t f2tf32(float f) {
    uint32_t u;
    asm("cvt.rn.tf32.f32 %0, %1;" : "=r"(u) : "f"(f));
    return u;
}

// ---------------------------------------------------------------------------
// tf32 mma.sync GEMM with bias: C[M,N] = A[M,K] @ B[K,N] + bias[N]
// CTA tile 128x128, K-tile 32, 256 threads (8 warps, each 32x64).
// mma.sync.aligned.m16n8k8.row.col.f32.tf32.tf32.f32
// smem per stage: As[128][36] (m-major, pad->conflict-free frag reads),
//                 Bs[32][132] (k-major, pad->conflict-free frag reads).
// Double-buffered, register prefetch, one __syncthreads per K-tile.
// ---------------------------------------------------------------------------
#define AS_STRIDE 36
#define BS_STRIDE 132
#define STAGE_FLOATS (128 * AS_STRIDE + 32 * BS_STRIDE)   // 4608 + 4224 = 8832

__global__ __launch_bounds__(256) void tf32_mma_gemm(
    const float* __restrict__ A, const float* __restrict__ B,
    const float* __restrict__ bias, float* __restrict__ C,
    int M, int N, int K)
{
    extern __shared__ float sm[];

    const int tid  = threadIdx.x;
    const int wid  = tid >> 5;
    const int lane = tid & 31;
    const int qr   = lane >> 2;   // 0..7
    const int qc   = lane & 3;    // 0..3

    const int m0 = blockIdx.y << 7;
    const int n0 = blockIdx.x << 7;
    const int wm = (wid & 3) << 5;   // warp m offset (0,32,64,96)
    const int wn = (wid >> 2) << 6;  // warp n offset (0,64)

    // global load base pointers
    const float* Ag = A + (size_t)(m0 + (tid >> 3)) * K + ((tid & 7) << 2);
    const float* Bg = B + (size_t)(tid >> 5) * N + n0 + ((tid & 31) << 2);

    // smem store base offsets (in floats)
    const int sAo = (tid >> 3) * AS_STRIDE + ((tid & 7) << 2);
    const int sBo = (tid >> 5) * BS_STRIDE + ((tid & 31) << 2);

    float acc[2][8][4];
    #pragma unroll
    for (int mt = 0; mt < 2; mt++)
        #pragma unroll
        for (int nt = 0; nt < 8; nt++)
            #pragma unroll
            for (int j = 0; j < 4; j++) acc[mt][nt][j] = 0.0f;

    float4 ra[4], rb[4];

    auto gload = [&](int k0) {
        #pragma unroll
        for (int i = 0; i < 4; i++) {
            ra[i] = *(const float4*)(Ag + (size_t)(i << 5) * K + k0);
            rb[i] = *(const float4*)(Bg + (size_t)(k0 + (i << 3)) * N);
        }
    };

    auto sstore = [&](int s) {
        float* As = sm + s * STAGE_FLOATS;
        float* Bs = As + 128 * AS_STRIDE;
        #pragma unroll
        for (int i = 0; i < 4; i++) {
            float4 av;
            av.x = __uint_as_float(f2tf32(ra[i].x));
            av.y = __uint_as_float(f2tf32(ra[i].y));
            av.z = __uint_as_float(f2tf32(ra[i].z));
            av.w = __uint_as_float(f2tf32(ra[i].w));
            *(float4*)&As[(i << 5) * AS_STRIDE + sAo] = av;
            float4 bv;
            bv.x = __uint_as_float(f2tf32(rb[i].x));
            bv.y = __uint_as_float(f2tf32(rb[i].y));
            bv.z = __uint_as_float(f2tf32(rb[i].z));
            bv.w = __uint_as_float(f2tf32(rb[i].w));
            *(float4*)&Bs[(i << 3) * BS_STRIDE + sBo] = bv;
        }
    };

    auto compute = [&](int s) {
        const uint32_t* As = (const uint32_t*)(sm + s * STAGE_FLOATS);
        const uint32_t* Bs = As + 128 * AS_STRIDE;
        #pragma unroll
        for (int kk = 0; kk < 4; kk++) {
            const int kb = kk << 3;
            uint32_t a[2][4], b[8][2];
            #pragma unroll
            for (int mt = 0; mt < 2; mt++) {
                const int row = wm + (mt << 4) + qr;
                a[mt][0] = As[row * AS_STRIDE + kb + qc];
                a[mt][1] = As[(row + 8) * AS_STRIDE + kb + qc];
                a[mt][2] = As[row * AS_STRIDE + kb + qc + 4];
                a[mt][3] = As[(row + 8) * AS_STRIDE + kb + qc + 4];
            }
            #pragma unroll
            for (int nt = 0; nt < 8; nt++) {
                const int col = wn + (nt << 3) + qr;
                b[nt][0] = Bs[(kb + qc) * BS_STRIDE + col];
                b[nt][1] = Bs[(kb + qc + 4) * BS_STRIDE + col];
            }
            #pragma unroll
            for (int mt = 0; mt < 2; mt++)
                #pragma unroll
                for (int nt = 0; nt < 8; nt++) {
                    asm volatile(
                        "mma.sync.aligned.m16n8k8.row.col.f32.tf32.tf32.f32 "
                        "{%0,%1,%2,%3}, {%4,%5,%6,%7}, {%8,%9}, {%0,%1,%2,%3};"
                        : "+f"(acc[mt][nt][0]), "+f"(acc[mt][nt][1]),
                          "+f"(acc[mt][nt][2]), "+f"(acc[mt][nt][3])
                        : "r"(a[mt][0]), "r"(a[mt][1]), "r"(a[mt][2]), "r"(a[mt][3]),
                          "r"(b[nt][0]), "r"(b[nt][1]));
                }
        }
    };

    const int KT = K >> 5;

    gload(0);
    sstore(0);
    __syncthreads();

    for (int t = 0; t < KT; ++t) {
        if (t + 1 < KT) gload((t + 1) << 5);
        compute(t & 1);
        if (t + 1 < KT) {
            sstore((t + 1) & 1);
            __syncthreads();
        }
    }

    // epilogue
    #pragma unroll
    for (int mt = 0; mt < 2; mt++) {
        const int row = m0 + wm + (mt << 4) + qr;
        #pragma unroll
        for (int nt = 0; nt < 8; nt++) {
            const int col = n0 + wn + (nt << 3) + (qc << 1);
            const float2 bv = *(const float2*)(bias + col);
            float2 o0, o1;
            o0.x = acc[mt][nt][0] + bv.x;
            o0.y = acc[mt][nt][1] + bv.y;
            o1.x = acc[mt][nt][2] + bv.x;
            o1.y = acc[mt][nt][3] + bv.y;
            *(float2*)(C + (size_t)row * N + col) = o0;
            *(float2*)(C + (size_t)(row + 8) * N + col) = o1;
        }
    }
}

// ---------------------------------------------------------------------------
// Flash attention (fp32, causal) — unchanged from R1 baseline.
// ---------------------------------------------------------------------------
#define TLDS 65

__global__ __launch_bounds__(256) void flash_attn_kernel(
    const float* __restrict__ qkv, float* __restrict__ outp)
{
    extern __shared__ float sm[];
    float* Qs = sm;
    float* Ks = Qs + 64 * TLDS;
    float* Vs = Ks + 64 * TLDS;
    float* Ps = Vs + 64 * TLDS;

    const int qt = blockIdx.x;
    const int h  = blockIdx.y;
    const int b  = blockIdx.z;

    const int tid = threadIdx.x;
    const int tx = tid & 15;
    const int ty = tid >> 4;

    const int q0 = qt * 64;
    const float scale = 0.125f;

    const float* qbase = qkv + (size_t)b * S_LEN * QKV_N + h * DH;
    const float* kbase = qbase + DMODEL;
    const float* vbase = qbase + 2 * DMODEL;

    for (int i = tid; i < 64 * 64; i += 256) {
        int r = i >> 6, d = i & 63;
        Qs[r * TLDS + d] = qbase[(size_t)(q0 + r) * QKV_N + d] * scale;
    }

    float m[4], l[4], acc[4][4];
    #pragma unroll
    for (int i = 0; i < 4; i++) {
        m[i] = -1e30f; l[i] = 0.0f;
        #pragma unroll
        for (int j = 0; j < 4; j++) acc[i][j] = 0.0f;
    }

    for (int kt = 0; kt <= qt; ++kt) {
        __syncthreads();
        const int k0 = kt * 64;
        for (int i = tid; i < 64 * 64; i += 256) {
            int r = i >> 6, d = i & 63;
            Ks[r * TLDS + d] = kbase[(size_t)(k0 + r) * QKV_N + d];
            Vs[r * TLDS + d] = vbase[(size_t)(k0 + r) * QKV_N + d];
        }
        __syncthreads();

        float s[4][4];
        #pragma unroll
        for (int i = 0; i < 4; i++)
            #pragma unroll
            for (int j = 0; j < 4; j++) s[i][j] = 0.0f;

        #pragma unroll 4
        for (int d = 0; d < 64; d++) {
            float qv[4], kv[4];
            #pragma unroll
            for (int i = 0; i < 4; i++) qv[i] = Qs[(ty * 4 + i) * TLDS + d];
            #pragma unroll
            for (int j = 0; j < 4; j++) kv[j] = Ks[(tx * 4 + j) * TLDS + d];
            #pragma unroll
            for (int i = 0; i < 4; i++)
                #pragma unroll
                for (int j = 0; j < 4; j++)
                    s[i][j] += qv[i] * kv[j];
        }

        if (kt == qt) {
            #pragma unroll
            for (int i = 0; i < 4; i++)
                #pragma unroll
                for (int j = 0; j < 4; j++)
                    if (tx * 4 + j > ty * 4 + i) s[i][j] = -1e30f;
        }

        #pragma unroll
        for (int i = 0; i < 4; i++) {
            float rm = fmaxf(fmaxf(s[i][0], s[i][1]), fmaxf(s[i][2], s[i][3]));
            #pragma unroll
            for (int o = 8; o >= 1; o >>= 1)
                rm = fmaxf(rm, __shfl_xor_sync(0xffffffffu, rm, o, 16));
            float mn = fmaxf(m[i], rm);
            float alpha = __expf(m[i] - mn);
            m[i] = mn;
            float rs = 0.0f;
            #pragma unroll
            for (int j = 0; j < 4; j++) {
                s[i][j] = __expf(s[i][j] - mn);
                rs += s[i][j];
            }
            #pragma unroll
            for (int o = 8; o >= 1; o >>= 1)
                rs += __shfl_xor_sync(0xffffffffu, rs, o, 16);
            l[i] = l[i] * alpha + rs;
            #pragma unroll
            for (int j = 0; j < 4; j++) acc[i][j] *= alpha;
        }

        #pragma unroll
        for (int i = 0; i < 4; i++)
            #pragma unroll
            for (int j = 0; j < 4; j++)
                Ps[(ty * 4 + i) * TLDS + tx * 4 + j] = s[i][j];
        __syncthreads();

        #pragma unroll 4
        for (int k = 0; k < 64; k++) {
            float pv[4], vv[4];
            #pragma unroll
            for (int i = 0; i < 4; i++) pv[i] = Ps[(ty * 4 + i) * TLDS + k];
            #pragma unroll
            for (int j = 0; j < 4; j++) vv[j] = Vs[k * TLDS + tx * 4 + j];
            #pragma unroll
            for (int i = 0; i < 4; i++)
                #pragma unroll
                for (int j = 0; j < 4; j++)
                    acc[i][j] += pv[i] * vv[j];
        }
    }

    #pragma unroll
    for (int i = 0; i < 4; i++) {
        float inv = 1.0f / l[i];
        int row = q0 + ty * 4 + i;
        float* orow = outp + ((size_t)b * S_LEN + row) * DMODEL + h * DH + tx * 4;
        #pragma unroll
        for (int j = 0; j < 4; j++) orow[j] = acc[i][j] * inv;
    }
}

// ---------------------------------------------------------------------------
// Launch
// ---------------------------------------------------------------------------
extern "C" void kernel_launch(void* const* d_in, const int* in_sizes, int n_in,
                              void* d_out, int out_size)
{
    const float* hidden = (const float*)d_in[0];
    const float* w_attn = (const float*)d_in[1];
    const float* b_attn = (const float*)d_in[2];
    const float* w_proj = (const float*)d_in[3];
    const float* b_proj = (const float*)d_in[4];
    float* out = (float*)d_out;

    float *qkv, *attn;
    cudaGetSymbolAddress((void**)&qkv, g_qkv);
    cudaGetSymbolAddress((void**)&attn, g_attn);

    const size_t gsm = (size_t)2 * STAGE_FLOATS * sizeof(float);  // 70656
    cudaFuncSetAttribute(tf32_mma_gemm,
                         cudaFuncAttributeMaxDynamicSharedMemorySize, (int)gsm);

    // 1) QKV projection (tf32 mma.sync): [8192,1024] @ [1024,3072] + bias
    tf32_mma_gemm<<<dim3(QKV_N / 128, NT / 128), 256, gsm>>>(
        hidden, w_attn, b_attn, qkv, NT, QKV_N, KDIM);

    // 2) causal flash attention
    {
        size_t smem = (size_t)4 * 64 * TLDS * sizeof(float);
        cudaFuncSetAttribute(flash_attn_kernel,
                             cudaFuncAttributeMaxDynamicSharedMemorySize, (int)smem);
        dim3 grid(S_LEN / 64, NH, BATCH);
        flash_attn_kernel<<<grid, 256, smem>>>(qkv, attn);
    }

    // 3) output projection (tf32 mma.sync): [8192,1024] @ [1024,1024] + bias
    tf32_mma_gemm<<<dim3(DMODEL / 128, NT / 128), 256, gsm>>>(
        attn, w_proj, b_proj, out, NT, DMODEL, KDIM);
}

// round 4
// speedup vs baseline: 2.6670x; 1.7259x over previous
#include <cuda_runtime.h>
#include <cuda_bf16.h>
#include <cstdint>
#include <cstddef>

// Problem constants
#define BATCH   4
#define S_LEN   2048
#define DMODEL  1024
#define NH      16
#define DH      64
#define NT      (BATCH * S_LEN)     // 8192 rows
#define QKV_N   (3 * DMODEL)        // 3072
#define KDIM    1024

// Scratch (device globals: allocation-free)
__device__ float g_qkv[(size_t)NT * QKV_N];    // [8192, 3072]
__device__ float g_attn[(size_t)NT * DMODEL];  // [8192, 1024]

__device__ __forceinline__ uint32_t f2tf32(float f) {
    uint32_t u;
    asm("cvt.rn.tf32.f32 %0, %1;" : "=r"(u) : "f"(f));
    return u;
}

// ---------------------------------------------------------------------------
// tf32 mma.sync GEMM with bias (unchanged from R3; passes at 438us QKV)
// ---------------------------------------------------------------------------
#define AS_STRIDE 36
#define BS_STRIDE 132
#define STAGE_FLOATS (128 * AS_STRIDE + 32 * BS_STRIDE)

__global__ __launch_bounds__(256) void tf32_mma_gemm(
    const float* __restrict__ A, const float* __restrict__ B,
    const float* __restrict__ bias, float* __restrict__ C,
    int M, int N, int K)
{
    extern __shared__ float sm[];

    const int tid  = threadIdx.x;
    const int wid  = tid >> 5;
    const int lane = tid & 31;
    const int qr   = lane >> 2;
    const int qc   = lane & 3;

    const int m0 = blockIdx.y << 7;
    const int n0 = blockIdx.x << 7;
    const int wm = (wid & 3) << 5;
    const int wn = (wid >> 2) << 6;

    const float* Ag = A + (size_t)(m0 + (tid >> 3)) * K + ((tid & 7) << 2);
    const float* Bg = B + (size_t)(tid >> 5) * N + n0 + ((tid & 31) << 2);

    const int sAo = (tid >> 3) * AS_STRIDE + ((tid & 7) << 2);
    const int sBo = (tid >> 5) * BS_STRIDE + ((tid & 31) << 2);

    float acc[2][8][4];
    #pragma unroll
    for (int mt = 0; mt < 2; mt++)
        #pragma unroll
        for (int nt = 0; nt < 8; nt++)
            #pragma unroll
            for (int j = 0; j < 4; j++) acc[mt][nt][j] = 0.0f;

    float4 ra[4], rb[4];

    auto gload = [&](int k0) {
        #pragma unroll
        for (int i = 0; i < 4; i++) {
            ra[i] = *(const float4*)(Ag + (size_t)(i << 5) * K + k0);
            rb[i] = *(const float4*)(Bg + (size_t)(k0 + (i << 3)) * N);
        }
    };

    auto sstore = [&](int s) {
        float* As = sm + s * STAGE_FLOATS;
        float* Bs = As + 128 * AS_STRIDE;
        #pragma unroll
        for (int i = 0; i < 4; i++) {
            float4 av;
            av.x = __uint_as_float(f2tf32(ra[i].x));
            av.y = __uint_as_float(f2tf32(ra[i].y));
            av.z = __uint_as_float(f2tf32(ra[i].z));
            av.w = __uint_as_float(f2tf32(ra[i].w));
            *(float4*)&As[(i << 5) * AS_STRIDE + sAo] = av;
            float4 bv;
            bv.x = __uint_as_float(f2tf32(rb[i].x));
            bv.y = __uint_as_float(f2tf32(rb[i].y));
            bv.z = __uint_as_float(f2tf32(rb[i].z));
            bv.w = __uint_as_float(f2tf32(rb[i].w));
            *(float4*)&Bs[(i << 3) * BS_STRIDE + sBo] = bv;
        }
    };

    auto compute = [&](int s) {
        const uint32_t* As = (const uint32_t*)(sm + s * STAGE_FLOATS);
        const uint32_t* Bs = As + 128 * AS_STRIDE;
        #pragma unroll
        for (int kk = 0; kk < 4; kk++) {
            const int kb = kk << 3;
            uint32_t a[2][4], b[8][2];
            #pragma unroll
            for (int mt = 0; mt < 2; mt++) {
                const int row = wm + (mt << 4) + qr;
                a[mt][0] = As[row * AS_STRIDE + kb + qc];
                a[mt][1] = As[(row + 8) * AS_STRIDE + kb + qc];
                a[mt][2] = As[row * AS_STRIDE + kb + qc + 4];
                a[mt][3] = As[(row + 8) * AS_STRIDE + kb + qc + 4];
            }
            #pragma unroll
            for (int nt = 0; nt < 8; nt++) {
                const int col = wn + (nt << 3) + qr;
                b[nt][0] = Bs[(kb + qc) * BS_STRIDE + col];
                b[nt][1] = Bs[(kb + qc + 4) * BS_STRIDE + col];
            }
            #pragma unroll
            for (int mt = 0; mt < 2; mt++)
                #pragma unroll
                for (int nt = 0; nt < 8; nt++) {
                    asm volatile(
                        "mma.sync.aligned.m16n8k8.row.col.f32.tf32.tf32.f32 "
                        "{%0,%1,%2,%3}, {%4,%5,%6,%7}, {%8,%9}, {%0,%1,%2,%3};"
                        : "+f"(acc[mt][nt][0]), "+f"(acc[mt][nt][1]),
                          "+f"(acc[mt][nt][2]), "+f"(acc[mt][nt][3])
                        : "r"(a[mt][0]), "r"(a[mt][1]), "r"(a[mt][2]), "r"(a[mt][3]),
                          "r"(b[nt][0]), "r"(b[nt][1]));
                }
        }
    };

    const int KT = K >> 5;

    gload(0);
    sstore(0);
    __syncthreads();

    for (int t = 0; t < KT; ++t) {
        if (t + 1 < KT) gload((t + 1) << 5);
        compute(t & 1);
        if (t + 1 < KT) {
            sstore((t + 1) & 1);
            __syncthreads();
        }
    }

    #pragma unroll
    for (int mt = 0; mt < 2; mt++) {
        const int row = m0 + wm + (mt << 4) + qr;
        #pragma unroll
        for (int nt = 0; nt < 8; nt++) {
            const int col = n0 + wn + (nt << 3) + (qc << 1);
            const float2 bv = *(const float2*)(bias + col);
            float2 o0, o1;
            o0.x = acc[mt][nt][0] + bv.x;
            o0.y = acc[mt][nt][1] + bv.y;
            o1.x = acc[mt][nt][2] + bv.x;
            o1.y = acc[mt][nt][3] + bv.y;
            *(float2*)(C + (size_t)row * N + col) = o0;
            *(float2*)(C + (size_t)(row + 8) * N + col) = o1;
        }
    }
}

// ---------------------------------------------------------------------------
// Tensor-core flash attention (tf32 mma.sync, causal).
// CTA: 128 q-rows x 64 k-cols per iter. 8 warps, each 16 q-rows x 64 cols.
// Q fragments persist in registers. K: smem [64][68] n-major. V: [64][72]
// n-major. P: smem [128][72] with col ^= (row&4) swizzle (conflict-free
// float2 stores AND A-frag loads).
// ---------------------------------------------------------------------------
#define KS_ST 68
#define VS_ST 72
#define PS_ST 72
#define FA_SMEM_FLOATS (64 * KS_ST + 64 * VS_ST + 128 * PS_ST)  // 18176

__global__ __launch_bounds__(256) void flash_attn_tc(
    const float* __restrict__ qkv, float* __restrict__ outp)
{
    extern __shared__ float sm[];
    float* Ks = sm;
    float* Vs = Ks + 64 * KS_ST;
    float* Ps = Vs + 64 * VS_ST;

    const int qt = blockIdx.x;   // 0..15 (128-row q tiles)
    const int h  = blockIdx.y;
    const int b  = blockIdx.z;

    const int tid  = threadIdx.x;
    const int wid  = tid >> 5;
    const int lane = tid & 31;
    const int qr   = lane >> 2;  // 0..7
    const int qc   = lane & 3;   // 0..3
    const int wq   = wid << 4;   // warp q-row offset
    const int q0   = qt << 7;

    const float* qbase = qkv + (size_t)b * S_LEN * QKV_N + h * DH;
    const float* kbase = qbase + DMODEL;
    const float* vbase = qbase + 2 * DMODEL;

    // Persistent Q fragments (pre-scaled, tf32)
    uint32_t qa[8][4];
    {
        const float* r0 = qbase + (size_t)(q0 + wq + qr) * QKV_N;
        const float* r1 = r0 + (size_t)8 * QKV_N;
        #pragma unroll
        for (int kc = 0; kc < 8; kc++) {
            qa[kc][0] = f2tf32(r0[kc * 8 + qc]     * 0.125f);
            qa[kc][1] = f2tf32(r1[kc * 8 + qc]     * 0.125f);
            qa[kc][2] = f2tf32(r0[kc * 8 + qc + 4] * 0.125f);
            qa[kc][3] = f2tf32(r1[kc * 8 + qc + 4] * 0.125f);
        }
    }

    float o[8][4];
    #pragma unroll
    for (int dt = 0; dt < 8; dt++)
        #pragma unroll
        for (int j = 0; j < 4; j++) o[dt][j] = 0.0f;
    float m0v = -1e30f, m1v = -1e30f, l0 = 0.0f, l1 = 0.0f;

    // K/V smem copy mapping: row = tid&63, 16-float segment = tid>>6
    const int cr = tid & 63;
    const int cc = (tid >> 6) << 4;
    const int swz = qr & 4;   // P-buffer column swizzle

    const int ktmax = 2 * qt + 2;
    for (int kt = 0; kt < ktmax; ++kt) {
        const int k0 = kt << 6;
        __syncthreads();   // protect Ks/Vs/Ps from previous iteration readers
        {
            const float* kg = kbase + (size_t)(k0 + cr) * QKV_N + cc;
            const float* vg = vbase + (size_t)(k0 + cr) * QKV_N + cc;
            float* kd = Ks + cr * KS_ST + cc;
            float* vd = Vs + cr * VS_ST + cc;
            #pragma unroll
            for (int j = 0; j < 16; j += 4) {
                float4 k4 = *(const float4*)(kg + j);
                float4 v4 = *(const float4*)(vg + j);
                float4 ko, vo;
                ko.x = __uint_as_float(f2tf32(k4.x));
                ko.y = __uint_as_float(f2tf32(k4.y));
                ko.z = __uint_as_float(f2tf32(k4.z));
                ko.w = __uint_as_float(f2tf32(k4.w));
                vo.x = __uint_as_float(f2tf32(v4.x));
                vo.y = __uint_as_float(f2tf32(v4.y));
                vo.z = __uint_as_float(f2tf32(v4.z));
                vo.w = __uint_as_float(f2tf32(v4.w));
                *(float4*)(kd + j) = ko;
                *(float4*)(vd + j) = vo;
            }
        }
        __syncthreads();

        // S = Q @ K^T  (B-frag: b0 = K[nt*8+qr][kb+qc], b1 = +4 in k)
        float s[8][4];
        #pragma unroll
        for (int nt = 0; nt < 8; nt++)
            #pragma unroll
            for (int j = 0; j < 4; j++) s[nt][j] = 0.0f;

        const uint32_t* Ku = (const uint32_t*)Ks;
        #pragma unroll
        for (int kc = 0; kc < 8; kc++) {
            const int kb = kc << 3;
            #pragma unroll
            for (int nt = 0; nt < 8; nt++) {
                uint32_t b0 = Ku[(nt * 8 + qr) * KS_ST + kb + qc];
                uint32_t b1 = Ku[(nt * 8 + qr) * KS_ST + kb + qc + 4];
                asm volatile(
                    "mma.sync.aligned.m16n8k8.row.col.f32.tf32.tf32.f32 "
                    "{%0,%1,%2,%3}, {%4,%5,%6,%7}, {%8,%9}, {%0,%1,%2,%3};"
                    : "+f"(s[nt][0]), "+f"(s[nt][1]), "+f"(s[nt][2]), "+f"(s[nt][3])
                    : "r"(qa[kc][0]), "r"(qa[kc][1]), "r"(qa[kc][2]), "r"(qa[kc][3]),
                      "r"(b0), "r"(b1));
            }
        }

        // causal mask (only tiles overlapping the diagonal)
        if (k0 + 63 > q0 + wq) {
            const int row0 = q0 + wq + qr;
            #pragma unroll
            for (int nt = 0; nt < 8; nt++) {
                const int col = k0 + nt * 8 + 2 * qc;
                if (col     > row0)     s[nt][0] = -1e30f;
                if (col + 1 > row0)     s[nt][1] = -1e30f;
                if (col     > row0 + 8) s[nt][2] = -1e30f;
                if (col + 1 > row0 + 8) s[nt][3] = -1e30f;
            }
        }

        // online softmax, row 0 (regs 0,1) and row 1 (regs 2,3)
        float rm0 = -1e30f, rm1 = -1e30f;
        #pragma unroll
        for (int nt = 0; nt < 8; nt++) {
            rm0 = fmaxf(rm0, fmaxf(s[nt][0], s[nt][1]));
            rm1 = fmaxf(rm1, fmaxf(s[nt][2], s[nt][3]));
        }
        rm0 = fmaxf(rm0, __shfl_xor_sync(0xffffffffu, rm0, 1));
        rm0 = fmaxf(rm0, __shfl_xor_sync(0xffffffffu, rm0, 2));
        rm1 = fmaxf(rm1, __shfl_xor_sync(0xffffffffu, rm1, 1));
        rm1 = fmaxf(rm1, __shfl_xor_sync(0xffffffffu, rm1, 2));

        const float mn0 = fmaxf(m0v, rm0);
        const float mn1 = fmaxf(m1v, rm1);
        const float al0 = __expf(m0v - mn0);
        const float al1 = __expf(m1v - mn1);
        m0v = mn0; m1v = mn1;

        float rs0 = 0.0f, rs1 = 0.0f;
        #pragma unroll
        for (int nt = 0; nt < 8; nt++) {
            s[nt][0] = __expf(s[nt][0] - mn0);
            s[nt][1] = __expf(s[nt][1] - mn0);
            s[nt][2] = __expf(s[nt][2] - mn1);
            s[nt][3] = __expf(s[nt][3] - mn1);
            rs0 += s[nt][0] + s[nt][1];
            rs1 += s[nt][2] + s[nt][3];
        }
        rs0 += __shfl_xor_sync(0xffffffffu, rs0, 1);
        rs0 += __shfl_xor_sync(0xffffffffu, rs0, 2);
        rs1 += __shfl_xor_sync(0xffffffffu, rs1, 1);
        rs1 += __shfl_xor_sync(0xffffffffu, rs1, 2);
        l0 = l0 * al0 + rs0;
        l1 = l1 * al1 + rs1;

        #pragma unroll
        for (int dt = 0; dt < 8; dt++) {
            o[dt][0] *= al0; o[dt][1] *= al0;
            o[dt][2] *= al1; o[dt][3] *= al1;
        }

        // store P fragments (tf32) with swizzle
        {
            float* p0 = Ps + (wq + qr) * PS_ST;
            float* p1 = p0 + 8 * PS_ST;
            #pragma unroll
            for (int nt = 0; nt < 8; nt++) {
                const int c = (nt * 8 + 2 * qc) ^ swz;
                float2 a, bb;
                a.x  = __uint_as_float(f2tf32(s[nt][0]));
                a.y  = __uint_as_float(f2tf32(s[nt][1]));
                bb.x = __uint_as_float(f2tf32(s[nt][2]));
                bb.y = __uint_as_float(f2tf32(s[nt][3]));
                *(float2*)(p0 + c) = a;
                *(float2*)(p1 + c) = bb;
            }
        }
        __syncthreads();

        // O += P @ V
        const uint32_t* Pu = (const uint32_t*)Ps;
        const uint32_t* Vu = (const uint32_t*)Vs;
        #pragma unroll
        for (int kc = 0; kc < 8; kc++) {
            const int kb = kc << 3;
            uint32_t a0 = Pu[(wq + qr) * PS_ST     + ((kb + qc) ^ swz)];
            uint32_t a1 = Pu[(wq + qr + 8) * PS_ST + ((kb + qc) ^ swz)];
            uint32_t a2 = Pu[(wq + qr) * PS_ST     + ((kb + qc + 4) ^ swz)];
            uint32_t a3 = Pu[(wq + qr + 8) * PS_ST + ((kb + qc + 4) ^ swz)];
            #pragma unroll
            for (int dt = 0; dt < 8; dt++) {
                uint32_t b0 = Vu[(kb + qc) * VS_ST + dt * 8 + qr];
                uint32_t b1 = Vu[(kb + qc + 4) * VS_ST + dt * 8 + qr];
                asm volatile(
                    "mma.sync.aligned.m16n8k8.row.col.f32.tf32.tf32.f32 "
                    "{%0,%1,%2,%3}, {%4,%5,%6,%7}, {%8,%9}, {%0,%1,%2,%3};"
                    : "+f"(o[dt][0]), "+f"(o[dt][1]), "+f"(o[dt][2]), "+f"(o[dt][3])
                    : "r"(a0), "r"(a1), "r"(a2), "r"(a3), "r"(b0), "r"(b1));
            }
        }
    }

    // normalize + write merged-heads output
    const float inv0 = 1.0f / l0;
    const float inv1 = 1.0f / l1;
    float* o0 = outp + ((size_t)b * S_LEN + q0 + wq + qr) * DMODEL + h * DH + 2 * qc;
    float* o1 = o0 + (size_t)8 * DMODEL;
    #pragma unroll
    for (int dt = 0; dt < 8; dt++) {
        float2 v0, v1;
        v0.x = o[dt][0] * inv0; v0.y = o[dt][1] * inv0;
        v1.x = o[dt][2] * inv1; v1.y = o[dt][3] * inv1;
        *(float2*)(o0 + dt * 8) = v0;
        *(float2*)(o1 + dt * 8) = v1;
    }
}

// ---------------------------------------------------------------------------
// Launch
// ---------------------------------------------------------------------------
extern "C" void kernel_launch(void* const* d_in, const int* in_sizes, int n_in,
                              void* d_out, int out_size)
{
    const float* hidden = (const float*)d_in[0];
    const float* w_attn = (const float*)d_in[1];
    const float* b_attn = (const float*)d_in[2];
    const float* w_proj = (const float*)d_in[3];
    const float* b_proj = (const float*)d_in[4];
    float* out = (float*)d_out;

    float *qkv, *attn;
    cudaGetSymbolAddress((void**)&qkv, g_qkv);
    cudaGetSymbolAddress((void**)&attn, g_attn);

    const size_t gsm = (size_t)2 * STAGE_FLOATS * sizeof(float);
    cudaFuncSetAttribute(tf32_mma_gemm,
                         cudaFuncAttributeMaxDynamicSharedMemorySize, (int)gsm);

    // 1) QKV projection
    tf32_mma_gemm<<<dim3(QKV_N / 128, NT / 128), 256, gsm>>>(
        hidden, w_attn, b_attn, qkv, NT, QKV_N, KDIM);

    // 2) causal flash attention (tensor cores)
    {
        const size_t fsm = (size_t)FA_SMEM_FLOATS * sizeof(float);  // 72704
        cudaFuncSetAttribute(flash_attn_tc,
                             cudaFuncAttributeMaxDynamicSharedMemorySize, (int)fsm);
        dim3 grid(S_LEN / 128, NH, BATCH);
        flash_attn_tc<<<grid, 256, fsm>>>(qkv, attn);
    }

    // 3) output projection
    tf32_mma_gemm<<<dim3(DMODEL / 128, NT / 128), 256, gsm>>>(
        attn, w_proj, b_proj, out, NT, DMODEL, KDIM);
}

// round 5
// speedup vs baseline: 2.8824x; 1.0807x over previous
#include <cuda_runtime.h>
#include <cuda_bf16.h>
#include <cstdint>
#include <cstddef>

// Problem constants
#define BATCH   4
#define S_LEN   2048
#define DMODEL  1024
#define NH      16
#define DH      64
#define NT      (BATCH * S_LEN)     // 8192 rows
#define QKV_N   (3 * DMODEL)        // 3072
#define KDIM    1024

// Scratch (device globals: allocation-free)
__device__ float g_qkv[(size_t)NT * QKV_N];      // [8192, 3072]
__device__ float g_attn[(size_t)NT * DMODEL];    // [8192, 1024] (tf32-rounded)
__device__ float g_hid[(size_t)NT * KDIM];       // hidden, tf32-rounded
__device__ float g_wqkv[(size_t)KDIM * QKV_N];   // c_attn_w, tf32-rounded
__device__ float g_wproj[(size_t)KDIM * DMODEL]; // c_proj_w, tf32-rounded

__device__ __forceinline__ uint32_t f2tf32(float f) {
    uint32_t u;
    asm("cvt.rn.tf32.f32 %0, %1;" : "=r"(u) : "f"(f));
    return u;
}
__device__ __forceinline__ void cp16(void* smem_dst, const void* gsrc) {
    uint32_t s = (uint32_t)__cvta_generic_to_shared(smem_dst);
    asm volatile("cp.async.cg.shared.global [%0], [%1], 16;"
                 :: "r"(s), "l"(gsrc) : "memory");
}

// ---------------------------------------------------------------------------
// tf32 rounding prep: out[i] = round_tf32(in[i]), n % 4 == 0
// ---------------------------------------------------------------------------
__global__ __launch_bounds__(256) void round_tf32_kernel(
    const float* __restrict__ in, float* __restrict__ out, int n4)
{
    int i = blockIdx.x * blockDim.x + threadIdx.x;
    if (i < n4) {
        float4 v = ((const float4*)in)[i];
        float4 o;
        o.x = __uint_as_float(f2tf32(v.x));
        o.y = __uint_as_float(f2tf32(v.y));
        o.z = __uint_as_float(f2tf32(v.z));
        o.w = __uint_as_float(f2tf32(v.w));
        ((float4*)out)[i] = o;
    }
}

// ---------------------------------------------------------------------------
// tf32 mma.sync GEMM with bias: C = A @ B + bias. Operands pre-rounded tf32.
// CTA 128x128, K-tile 32, 256 threads (8 warps @ 32x64), cp.async 3-stage,
// __launch_bounds__(256,2) -> 2 CTAs/SM.
// ---------------------------------------------------------------------------
#define AS_STRIDE 36
#define BS_STRIDE 132
#define STAGE_FLOATS (128 * AS_STRIDE + 32 * BS_STRIDE)   // 8832
#define STAGES 3

__global__ __launch_bounds__(256, 2) void tf32_mma_gemm(
    const float* __restrict__ A, const float* __restrict__ B,
    const float* __restrict__ bias, float* __restrict__ C,
    int M, int N, int K)
{
    extern __shared__ float sm[];

    const int tid  = threadIdx.x;
    const int wid  = tid >> 5;
    const int lane = tid & 31;
    const int qr   = lane >> 2;
    const int qc   = lane & 3;

    const int m0 = blockIdx.y << 7;
    const int n0 = blockIdx.x << 7;
    const int wm = (wid & 3) << 5;
    const int wn = (wid >> 2) << 6;

    const float* Ag = A + (size_t)(m0 + (tid >> 3)) * K + ((tid & 7) << 2);
    const float* Bg = B + (size_t)(tid >> 5) * N + n0 + ((tid & 31) << 2);

    const int sAo = (tid >> 3) * AS_STRIDE + ((tid & 7) << 2);
    const int sBo = (tid >> 5) * BS_STRIDE + ((tid & 31) << 2);

    float acc[2][8][4];
    #pragma unroll
    for (int mt = 0; mt < 2; mt++)
        #pragma unroll
        for (int nt = 0; nt < 8; nt++)
            #pragma unroll
            for (int j = 0; j < 4; j++) acc[mt][nt][j] = 0.0f;

    auto issue = [&](int s, int k0) {
        float* As = sm + s * STAGE_FLOATS;
        float* Bs = As + 128 * AS_STRIDE;
        #pragma unroll
        for (int i = 0; i < 4; i++) {
            cp16(&As[(i << 5) * AS_STRIDE + sAo], Ag + (size_t)(i << 5) * K + k0);
            cp16(&Bs[(i << 3) * BS_STRIDE + sBo], Bg + (size_t)(k0 + (i << 3)) * N);
        }
        asm volatile("cp.async.commit_group;" ::: "memory");
    };

    auto compute = [&](int s) {
        const uint32_t* As = (const uint32_t*)(sm + s * STAGE_FLOATS);
        const uint32_t* Bs = As + 128 * AS_STRIDE;
        #pragma unroll
        for (int kk = 0; kk < 4; kk++) {
            const int kb = kk << 3;
            uint32_t a[2][4], b[8][2];
            #pragma unroll
            for (int mt = 0; mt < 2; mt++) {
                const int row = wm + (mt << 4) + qr;
                a[mt][0] = As[row * AS_STRIDE + kb + qc];
                a[mt][1] = As[(row + 8) * AS_STRIDE + kb + qc];
                a[mt][2] = As[row * AS_STRIDE + kb + qc + 4];
                a[mt][3] = As[(row + 8) * AS_STRIDE + kb + qc + 4];
            }
            #pragma unroll
            for (int nt = 0; nt < 8; nt++) {
                const int col = wn + (nt << 3) + qr;
                b[nt][0] = Bs[(kb + qc) * BS_STRIDE + col];
                b[nt][1] = Bs[(kb + qc + 4) * BS_STRIDE + col];
            }
            #pragma unroll
            for (int mt = 0; mt < 2; mt++)
                #pragma unroll
                for (int nt = 0; nt < 8; nt++) {
                    asm volatile(
                        "mma.sync.aligned.m16n8k8.row.col.f32.tf32.tf32.f32 "
                        "{%0,%1,%2,%3}, {%4,%5,%6,%7}, {%8,%9}, {%0,%1,%2,%3};"
                        : "+f"(acc[mt][nt][0]), "+f"(acc[mt][nt][1]),
                          "+f"(acc[mt][nt][2]), "+f"(acc[mt][nt][3])
                        : "r"(a[mt][0]), "r"(a[mt][1]), "r"(a[mt][2]), "r"(a[mt][3]),
                          "r"(b[nt][0]), "r"(b[nt][1]));
                }
        }
    };

    const int KT = K >> 5;

    #pragma unroll
    for (int s = 0; s < STAGES - 1; s++) issue(s, s << 5);

    for (int t = 0; t < KT; ++t) {
        asm volatile("cp.async.wait_group %0;" :: "n"(STAGES - 2) : "memory");
        __syncthreads();
        if (t + STAGES - 1 < KT)
            issue((t + STAGES - 1) % STAGES, (t + STAGES - 1) << 5);
        compute(t % STAGES);
    }

    #pragma unroll
    for (int mt = 0; mt < 2; mt++) {
        const int row = m0 + wm + (mt << 4) + qr;
        #pragma unroll
        for (int nt = 0; nt < 8; nt++) {
            const int col = n0 + wn + (nt << 3) + (qc << 1);
            const float2 bv = *(const float2*)(bias + col);
            float2 o0, o1;
            o0.x = acc[mt][nt][0] + bv.x;
            o0.y = acc[mt][nt][1] + bv.y;
            o1.x = acc[mt][nt][2] + bv.x;
            o1.y = acc[mt][nt][3] + bv.y;
            *(float2*)(C + (size_t)row * N + col) = o0;
            *(float2*)(C + (size_t)(row + 8) * N + col) = o1;
        }
    }
}

// ---------------------------------------------------------------------------
// Tensor-core flash attention (tf32 mma.sync, causal) — as R4, but output is
// tf32-rounded (feeds the proj GEMM, which assumes pre-rounded operands).
// ---------------------------------------------------------------------------
#define KS_ST 68
#define VS_ST 72
#define PS_ST 72
#define FA_SMEM_FLOATS (64 * KS_ST + 64 * VS_ST + 128 * PS_ST)

__global__ __launch_bounds__(256) void flash_attn_tc(
    const float* __restrict__ qkv, float* __restrict__ outp)
{
    extern __shared__ float sm[];
    float* Ks = sm;
    float* Vs = Ks + 64 * KS_ST;
    float* Ps = Vs + 64 * VS_ST;

    const int qt = blockIdx.x;
    const int h  = blockIdx.y;
    const int b  = blockIdx.z;

    const int tid  = threadIdx.x;
    const int wid  = tid >> 5;
    const int lane = tid & 31;
    const int qr   = lane >> 2;
    const int qc   = lane & 3;
    const int wq   = wid << 4;
    const int q0   = qt << 7;

    const float* qbase = qkv + (size_t)b * S_LEN * QKV_N + h * DH;
    const float* kbase = qbase + DMODEL;
    const float* vbase = qbase + 2 * DMODEL;

    uint32_t qa[8][4];
    {
        const float* r0 = qbase + (size_t)(q0 + wq + qr) * QKV_N;
        const float* r1 = r0 + (size_t)8 * QKV_N;
        #pragma unroll
        for (int kc = 0; kc < 8; kc++) {
            qa[kc][0] = f2tf32(r0[kc * 8 + qc]     * 0.125f);
            qa[kc][1] = f2tf32(r1[kc * 8 + qc]     * 0.125f);
            qa[kc][2] = f2tf32(r0[kc * 8 + qc + 4] * 0.125f);
            qa[kc][3] = f2tf32(r1[kc * 8 + qc + 4] * 0.125f);
        }
    }

    float o[8][4];
    #pragma unroll
    for (int dt = 0; dt < 8; dt++)
        #pragma unroll
        for (int j = 0; j < 4; j++) o[dt][j] = 0.0f;
    float m0v = -1e30f, m1v = -1e30f, l0 = 0.0f, l1 = 0.0f;

    const int cr = tid & 63;
    const int cc = (tid >> 6) << 4;
    const int swz = qr & 4;

    const int ktmax = 2 * qt + 2;
    for (int kt = 0; kt < ktmax; ++kt) {
        const int k0 = kt << 6;
        __syncthreads();
        {
            const float* kg = kbase + (size_t)(k0 + cr) * QKV_N + cc;
            const float* vg = vbase + (size_t)(k0 + cr) * QKV_N + cc;
            float* kd = Ks + cr * KS_ST + cc;
            float* vd = Vs + cr * VS_ST + cc;
            #pragma unroll
            for (int j = 0; j < 16; j += 4) {
                float4 k4 = *(const float4*)(kg + j);
                float4 v4 = *(const float4*)(vg + j);
                float4 ko, vo;
                ko.x = __uint_as_float(f2tf32(k4.x));
                ko.y = __uint_as_float(f2tf32(k4.y));
                ko.z = __uint_as_float(f2tf32(k4.z));
                ko.w = __uint_as_float(f2tf32(k4.w));
                vo.x = __uint_as_float(f2tf32(v4.x));
                vo.y = __uint_as_float(f2tf32(v4.y));
                vo.z = __uint_as_float(f2tf32(v4.z));
                vo.w = __uint_as_float(f2tf32(v4.w));
                *(float4*)(kd + j) = ko;
                *(float4*)(vd + j) = vo;
            }
        }
        __syncthreads();

        float s[8][4];
        #pragma unroll
        for (int nt = 0; nt < 8; nt++)
            #pragma unroll
            for (int j = 0; j < 4; j++) s[nt][j] = 0.0f;

        const uint32_t* Ku = (const uint32_t*)Ks;
        #pragma unroll
        for (int kc = 0; kc < 8; kc++) {
            const int kb = kc << 3;
            #pragma unroll
            for (int nt = 0; nt < 8; nt++) {
                uint32_t b0 = Ku[(nt * 8 + qr) * KS_ST + kb + qc];
                uint32_t b1 = Ku[(nt * 8 + qr) * KS_ST + kb + qc + 4];
                asm volatile(
                    "mma.sync.aligned.m16n8k8.row.col.f32.tf32.tf32.f32 "
                    "{%0,%1,%2,%3}, {%4,%5,%6,%7}, {%8,%9}, {%0,%1,%2,%3};"
                    : "+f"(s[nt][0]), "+f"(s[nt][1]), "+f"(s[nt][2]), "+f"(s[nt][3])
                    : "r"(qa[kc][0]), "r"(qa[kc][1]), "r"(qa[kc][2]), "r"(qa[kc][3]),
                      "r"(b0), "r"(b1));
            }
        }

        if (k0 + 63 > q0 + wq) {
            const int row0 = q0 + wq + qr;
            #pragma unroll
            for (int nt = 0; nt < 8; nt++) {
                const int col = k0 + nt * 8 + 2 * qc;
                if (col     > row0)     s[nt][0] = -1e30f;
                if (col + 1 > row0)     s[nt][1] = -1e30f;
                if (col     > row0 + 8) s[nt][2] = -1e30f;
                if (col + 1 > row0 + 8) s[nt][3] = -1e30f;
            }
        }

        float rm0 = -1e30f, rm1 = -1e30f;
        #pragma unroll
        for (int nt = 0; nt < 8; nt++) {
            rm0 = fmaxf(rm0, fmaxf(s[nt][0], s[nt][1]));
            rm1 = fmaxf(rm1, fmaxf(s[nt][2], s[nt][3]));
        }
        rm0 = fmaxf(rm0, __shfl_xor_sync(0xffffffffu, rm0, 1));
        rm0 = fmaxf(rm0, __shfl_xor_sync(0xffffffffu, rm0, 2));
        rm1 = fmaxf(rm1, __shfl_xor_sync(0xffffffffu, rm1, 1));
        rm1 = fmaxf(rm1, __shfl_xor_sync(0xffffffffu, rm1, 2));

        const float mn0 = fmaxf(m0v, rm0);
        const float mn1 = fmaxf(m1v, rm1);
        const float al0 = __expf(m0v - mn0);
        const float al1 = __expf(m1v - mn1);
        m0v = mn0; m1v = mn1;

        float rs0 = 0.0f, rs1 = 0.0f;
        #pragma unroll
        for (int nt = 0; nt < 8; nt++) {
            s[nt][0] = __expf(s[nt][0] - mn0);
            s[nt][1] = __expf(s[nt][1] - mn0);
            s[nt][2] = __expf(s[nt][2] - mn1);
            s[nt][3] = __expf(s[nt][3] - mn1);
            rs0 += s[nt][0] + s[nt][1];
            rs1 += s[nt][2] + s[nt][3];
        }
        rs0 += __shfl_xor_sync(0xffffffffu, rs0, 1);
        rs0 += __shfl_xor_sync(0xffffffffu, rs0, 2);
        rs1 += __shfl_xor_sync(0xffffffffu, rs1, 1);
        rs1 += __shfl_xor_sync(0xffffffffu, rs1, 2);
        l0 = l0 * al0 + rs0;
        l1 = l1 * al1 + rs1;

        #pragma unroll
        for (int dt = 0; dt < 8; dt++) {
            o[dt][0] *= al0; o[dt][1] *= al0;
            o[dt][2] *= al1; o[dt][3] *= al1;
        }

        {
            float* p0 = Ps + (wq + qr) * PS_ST;
            float* p1 = p0 + 8 * PS_ST;
            #pragma unroll
            for (int nt = 0; nt < 8; nt++) {
                const int c = (nt * 8 + 2 * qc) ^ swz;
                float2 a, bb;
                a.x  = __uint_as_float(f2tf32(s[nt][0]));
                a.y  = __uint_as_float(f2tf32(s[nt][1]));
                bb.x = __uint_as_float(f2tf32(s[nt][2]));
                bb.y = __uint_as_float(f2tf32(s[nt][3]));
                *(float2*)(p0 + c) = a;
                *(float2*)(p1 + c) = bb;
            }
        }
        __syncthreads();

        const uint32_t* Pu = (const uint32_t*)Ps;
        const uint32_t* Vu = (const uint32_t*)Vs;
        #pragma unroll
        for (int kc = 0; kc < 8; kc++) {
            const int kb = kc << 3;
            uint32_t a0 = Pu[(wq + qr) * PS_ST     + ((kb + qc) ^ swz)];
            uint32_t a1 = Pu[(wq + qr + 8) * PS_ST + ((kb + qc) ^ swz)];
            uint32_t a2 = Pu[(wq + qr) * PS_ST     + ((kb + qc + 4) ^ swz)];
            uint32_t a3 = Pu[(wq + qr + 8) * PS_ST + ((kb + qc + 4) ^ swz)];
            #pragma unroll
            for (int dt = 0; dt < 8; dt++) {
                uint32_t b0 = Vu[(kb + qc) * VS_ST + dt * 8 + qr];
                uint32_t b1 = Vu[(kb + qc + 4) * VS_ST + dt * 8 + qr];
                asm volatile(
                    "mma.sync.aligned.m16n8k8.row.col.f32.tf32.tf32.f32 "
                    "{%0,%1,%2,%3}, {%4,%5,%6,%7}, {%8,%9}, {%0,%1,%2,%3};"
                    : "+f"(o[dt][0]), "+f"(o[dt][1]), "+f"(o[dt][2]), "+f"(o[dt][3])
                    : "r"(a0), "r"(a1), "r"(a2), "r"(a3), "r"(b0), "r"(b1));
            }
        }
    }

    const float inv0 = 1.0f / l0;
    const float inv1 = 1.0f / l1;
    float* o0 = outp + ((size_t)b * S_LEN + q0 + wq + qr) * DMODEL + h * DH + 2 * qc;
    float* o1 = o0 + (size_t)8 * DMODEL;
    #pragma unroll
    for (int dt = 0; dt < 8; dt++) {
        float2 v0, v1;
        v0.x = __uint_as_float(f2tf32(o[dt][0] * inv0));
        v0.y = __uint_as_float(f2tf32(o[dt][1] * inv0));
        v1.x = __uint_as_float(f2tf32(o[dt][2] * inv1));
        v1.y = __uint_as_float(f2tf32(o[dt][3] * inv1));
        *(float2*)(o0 + dt * 8) = v0;
        *(float2*)(o1 + dt * 8) = v1;
    }
}

// ---------------------------------------------------------------------------
// Launch
// ---------------------------------------------------------------------------
extern "C" void kernel_launch(void* const* d_in, const int* in_sizes, int n_in,
                              void* d_out, int out_size)
{
    const float* hidden = (const float*)d_in[0];
    const float* w_attn = (const float*)d_in[1];
    const float* b_attn = (const float*)d_in[2];
    const float* w_proj = (const float*)d_in[3];
    const float* b_proj = (const float*)d_in[4];
    float* out = (float*)d_out;

    float *qkv, *attn, *hid, *wq, *wp;
    cudaGetSymbolAddress((void**)&qkv,  g_qkv);
    cudaGetSymbolAddress((void**)&attn, g_attn);
    cudaGetSymbolAddress((void**)&hid,  g_hid);
    cudaGetSymbolAddress((void**)&wq,   g_wqkv);
    cudaGetSymbolAddress((void**)&wp,   g_wproj);

    // 0) tf32-round GEMM operands
    {
        int n4;
        n4 = (NT * KDIM) / 4;
        round_tf32_kernel<<<(n4 + 255) / 256, 256>>>(hidden, hid, n4);
        n4 = (KDIM * QKV_N) / 4;
        round_tf32_kernel<<<(n4 + 255) / 256, 256>>>(w_attn, wq, n4);
        n4 = (KDIM * DMODEL) / 4;
        round_tf32_kernel<<<(n4 + 255) / 256, 256>>>(w_proj, wp, n4);
    }

    const size_t gsm = (size_t)STAGES * STAGE_FLOATS * sizeof(float); // 105984
    cudaFuncSetAttribute(tf32_mma_gemm,
                         cudaFuncAttributeMaxDynamicSharedMemorySize, (int)gsm);

    // 1) QKV projection
    tf32_mma_gemm<<<dim3(QKV_N / 128, NT / 128), 256, gsm>>>(
        hid, wq, b_attn, qkv, NT, QKV_N, KDIM);

    // 2) causal flash attention (tensor cores)
    {
        const size_t fsm = (size_t)FA_SMEM_FLOATS * sizeof(float);
        cudaFuncSetAttribute(flash_attn_tc,
                             cudaFuncAttributeMaxDynamicSharedMemorySize, (int)fsm);
        dim3 grid(S_LEN / 128, NH, BATCH);
        flash_attn_tc<<<grid, 256, fsm>>>(qkv, attn);
    }

    // 3) output projection
    tf32_mma_gemm<<<dim3(DMODEL / 128, NT / 128), 256, gsm>>>(
        attn, wp, b_proj, out, NT, DMODEL, KDIM);
}

// round 6
// speedup vs baseline: 3.2136x; 1.1149x over previous
#include <cuda_runtime.h>
#include <cuda_bf16.h>
#include <cstdint>
#include <cstddef>

// Problem constants
#define BATCH   4
#define S_LEN   2048
#define DMODEL  1024
#define NH      16
#define DH      64
#define NT      (BATCH * S_LEN)     // 8192 rows
#define QKV_N   (3 * DMODEL)        // 3072
#define KDIM    1024

// Scratch (device globals: allocation-free)
__device__ float g_qkv[(size_t)NT * QKV_N];       // [8192,3072], tf32-rounded
__device__ float g_attn[(size_t)NT * DMODEL];     // [8192,1024], packed-A layout, tf32
__device__ float g_hid_p[(size_t)NT * KDIM];      // hidden, packed-A, tf32
__device__ float g_wqkv_p[(size_t)KDIM * QKV_N];  // c_attn_w, packed-B, tf32
__device__ float g_wproj_p[(size_t)KDIM * DMODEL];// c_proj_w, packed-B, tf32

__device__ __forceinline__ uint32_t f2tf32(float f) {
    uint32_t u;
    asm("cvt.rn.tf32.f32 %0, %1;" : "=r"(u) : "f"(f));
    return u;
}
__device__ __forceinline__ float rtf(float f) { return __uint_as_float(f2tf32(f)); }
__device__ __forceinline__ void cp16(void* smem_dst, const void* gsrc) {
    uint32_t s = (uint32_t)__cvta_generic_to_shared(smem_dst);
    asm volatile("cp.async.cg.shared.global [%0], [%1], 16;"
                 :: "r"(s), "l"(gsrc) : "memory");
}
// fragment-order permutation within an 8-k group: slot j holds original k(j)
__device__ __host__ __forceinline__ int kofj(int j) { return (j >> 1) + ((j & 1) << 2); }

// ---------------------------------------------------------------------------
// Prep: pack A  (row-major [M][K] -> same, intra-8-k permuted, tf32-rounded)
// out[m][g*8+j] = round(in[m][g*8 + kofj(j)])
// ---------------------------------------------------------------------------
__global__ __launch_bounds__(256) void pack_a_kernel(
    const float* __restrict__ in, float* __restrict__ out, int K)
{
    const int t = blockIdx.x * blockDim.x + threadIdx.x;
    const int off = t << 2;                 // output float offset (float4)
    const int m = off / K;
    const int kp = off % K;
    const int g8 = kp & ~7;
    const int jb = kp & 7;                  // 0 or 4
    const float* row = in + (size_t)m * K + g8;
    float4 o;
    o.x = rtf(row[kofj(jb + 0)]);
    o.y = rtf(row[kofj(jb + 1)]);
    o.z = rtf(row[kofj(jb + 2)]);
    o.w = rtf(row[kofj(jb + 3)]);
    *(float4*)(out + off) = o;
}

// ---------------------------------------------------------------------------
// Prep: pack B  (row-major [K][N] -> [K/8][N][8] with intra-8 perm, tf32)
// out[((k>>3)*N + n)*8 + j] = round(in[(kg*8 + kofj(j))*N + n])
// ---------------------------------------------------------------------------
__global__ __launch_bounds__(256) void pack_b_kernel(
    const float* __restrict__ in, float* __restrict__ out, int N)
{
    const int t = blockIdx.x * blockDim.x + threadIdx.x;
    const size_t off = (size_t)t << 2;      // output float offset
    const int j0 = (int)(off & 7);          // 0 or 4
    const size_t lin8 = off >> 3;           // kg*N + n
    const int kg = (int)(lin8 / N);
    const int n  = (int)(lin8 % N);
    const float* base = in + (size_t)kg * 8 * N + n;
    float4 o;
    o.x = rtf(base[(size_t)kofj(j0 + 0) * N]);
    o.y = rtf(base[(size_t)kofj(j0 + 1) * N]);
    o.z = rtf(base[(size_t)kofj(j0 + 2) * N]);
    o.w = rtf(base[(size_t)kofj(j0 + 3) * N]);
    *(float4*)(out + off) = o;
}

// ---------------------------------------------------------------------------
// tf32 mma.sync GEMM with bias: C = A @ B + bias.
// A in packed-A layout [M][K], B in packed-B layout [K/8][N][8], both tf32.
// CTA 128x128, K-tile 32, 256 threads (8 warps @ 32x64), cp.async 3 stages,
// 2 CTAs/SM. Fragment loads are all LDS.64, conflict-free.
// round_out != 0 -> tf32-round outputs (QKV GEMM; feeds attention).
// ---------------------------------------------------------------------------
#define A_ST 40
#define AS_FLOATS (128 * A_ST)              // 5120
#define BS_FLOATS (4 * 128 * 8)             // 4096
#define STAGE_FLOATS (AS_FLOATS + BS_FLOATS)// 9216 (36 KB)
#define STAGES 3

__global__ __launch_bounds__(256, 2) void tf32_mma_gemm(
    const float* __restrict__ A, const float* __restrict__ B,
    const float* __restrict__ bias, float* __restrict__ C,
    int M, int N, int K, int round_out)
{
    extern __shared__ float sm[];

    const int tid  = threadIdx.x;
    const int wid  = tid >> 5;
    const int lane = tid & 31;
    const int qr   = lane >> 2;
    const int qc   = lane & 3;

    const int m0 = blockIdx.y << 7;
    const int n0 = blockIdx.x << 7;
    const int wm = (wid & 3) << 5;
    const int wn = (wid >> 2) << 6;

    const float* Ag  = A + (size_t)(m0 + (tid >> 3)) * K + ((tid & 7) << 2);
    const float* Bgk = B + (size_t)n0 * 8;   // + kg*N*8 + rem per stage

    const int sAo = (tid >> 3) * A_ST + ((tid & 7) << 2);

    float acc[2][8][4];
    #pragma unroll
    for (int mt = 0; mt < 2; mt++)
        #pragma unroll
        for (int nt = 0; nt < 8; nt++)
            #pragma unroll
            for (int j = 0; j < 4; j++) acc[mt][nt][j] = 0.0f;

    const int KT = K >> 5;

    auto issue = [&](int t) {
        if (t < KT) {
            const int k0 = t << 5;
            float* base = sm + (t % STAGES) * STAGE_FLOATS;
            #pragma unroll
            for (int i = 0; i < 4; i++)
                cp16(base + sAo + (i << 5) * A_ST, Ag + (size_t)(i << 5) * K + k0);
            const float* bsrc = Bgk + (size_t)(k0 >> 3) * N * 8;
            #pragma unroll
            for (int i = 0; i < 4; i++) {
                const int off = ((i << 8) + tid) << 2;   // 0..16380
                const int kg  = off >> 10;
                const int rem = off & 1023;
                cp16(base + AS_FLOATS + off, bsrc + (size_t)kg * N * 8 + rem);
            }
        }
        asm volatile("cp.async.commit_group;" ::: "memory");
    };

    auto compute = [&](int s) {
        const uint32_t* As = (const uint32_t*)(sm + s * STAGE_FLOATS);
        const uint32_t* Bs = As + AS_FLOATS;
        #pragma unroll
        for (int kk = 0; kk < 4; kk++) {
            uint2 ap[2][2], bp[8];
            #pragma unroll
            for (int mt = 0; mt < 2; mt++) {
                const int row = wm + (mt << 4) + qr;
                ap[mt][0] = *(const uint2*)&As[row * A_ST + (kk << 3) + 2 * qc];
                ap[mt][1] = *(const uint2*)&As[(row + 8) * A_ST + (kk << 3) + 2 * qc];
            }
            #pragma unroll
            for (int nt = 0; nt < 8; nt++) {
                const int col = wn + (nt << 3) + qr;
                bp[nt] = *(const uint2*)&Bs[(kk << 10) + (col << 3) + 2 * qc];
            }
            #pragma unroll
            for (int mt = 0; mt < 2; mt++)
                #pragma unroll
                for (int nt = 0; nt < 8; nt++) {
                    asm volatile(
                        "mma.sync.aligned.m16n8k8.row.col.f32.tf32.tf32.f32 "
                        "{%0,%1,%2,%3}, {%4,%5,%6,%7}, {%8,%9}, {%0,%1,%2,%3};"
                        : "+f"(acc[mt][nt][0]), "+f"(acc[mt][nt][1]),
                          "+f"(acc[mt][nt][2]), "+f"(acc[mt][nt][3])
                        : "r"(ap[mt][0].x), "r"(ap[mt][1].x),
                          "r"(ap[mt][0].y), "r"(ap[mt][1].y),
                          "r"(bp[nt].x), "r"(bp[nt].y));
                }
        }
    };

    issue(0);
    issue(1);

    for (int t = 0; t < KT; ++t) {
        asm volatile("cp.async.wait_group 1;" ::: "memory");
        __syncthreads();
        issue(t + 2);
        compute(t % STAGES);
    }

    #pragma unroll
    for (int mt = 0; mt < 2; mt++) {
        const int row = m0 + wm + (mt << 4) + qr;
        #pragma unroll
        for (int nt = 0; nt < 8; nt++) {
            const int col = n0 + wn + (nt << 3) + (qc << 1);
            const float2 bv = *(const float2*)(bias + col);
            float2 o0, o1;
            o0.x = acc[mt][nt][0] + bv.x;
            o0.y = acc[mt][nt][1] + bv.y;
            o1.x = acc[mt][nt][2] + bv.x;
            o1.y = acc[mt][nt][3] + bv.y;
            if (round_out) {
                o0.x = rtf(o0.x); o0.y = rtf(o0.y);
                o1.x = rtf(o1.x); o1.y = rtf(o1.y);
            }
            *(float2*)(C + (size_t)row * N + col) = o0;
            *(float2*)(C + (size_t)(row + 8) * N + col) = o1;
        }
    }
}

// ---------------------------------------------------------------------------
// Tensor-core flash attention (tf32 mma.sync, causal).
// Inputs pre-rounded to tf32 (QKV GEMM epilogue) -> raw cp.async K/V loads,
// 3-stage pipelined. Output written tf32-rounded in packed-A layout.
// ---------------------------------------------------------------------------
#define KS_ST 68
#define VS_ST 72
#define PS_ST 72
#define KV_STAGE (64 * KS_ST + 64 * VS_ST)          // 8960 floats
#define FA_SMEM_FLOATS (3 * KV_STAGE + 128 * PS_ST) // 36096 (141 KB)

__global__ __launch_bounds__(256) void flash_attn_tc(
    const float* __restrict__ qkv, float* __restrict__ outp)
{
    extern __shared__ float sm[];
    float* Ps = sm + 3 * KV_STAGE;

    const int qt = blockIdx.x;
    const int h  = blockIdx.y;
    const int b  = blockIdx.z;

    const int tid  = threadIdx.x;
    const int wid  = tid >> 5;
    const int lane = tid & 31;
    const int qr   = lane >> 2;
    const int qc   = lane & 3;
    const int wq   = wid << 4;
    const int q0   = qt << 7;

    const float* qbase = qkv + (size_t)b * S_LEN * QKV_N + h * DH;
    const float* kbase = qbase + DMODEL;
    const float* vbase = qbase + 2 * DMODEL;

    // Persistent Q fragments (x0.125 is exact; inputs already tf32)
    uint32_t qa[8][4];
    {
        const float* r0 = qbase + (size_t)(q0 + wq + qr) * QKV_N;
        const float* r1 = r0 + (size_t)8 * QKV_N;
        #pragma unroll
        for (int kc = 0; kc < 8; kc++) {
            qa[kc][0] = __float_as_uint(r0[kc * 8 + qc]     * 0.125f);
            qa[kc][1] = __float_as_uint(r1[kc * 8 + qc]     * 0.125f);
            qa[kc][2] = __float_as_uint(r0[kc * 8 + qc + 4] * 0.125f);
            qa[kc][3] = __float_as_uint(r1[kc * 8 + qc + 4] * 0.125f);
        }
    }

    float o[8][4];
    #pragma unroll
    for (int dt = 0; dt < 8; dt++)
        #pragma unroll
        for (int j = 0; j < 4; j++) o[dt][j] = 0.0f;
    float m0v = -1e30f, m1v = -1e30f, l0 = 0.0f, l1 = 0.0f;

    const int cr = tid & 63;
    const int cc = (tid >> 6) << 4;
    const int swz = qr & 4;

    const int ktmax = 2 * qt + 2;

    auto issue = [&](int t) {
        if (t < ktmax) {
            const int k0 = t << 6;
            float* Kd = sm + (t % 3) * KV_STAGE + cr * KS_ST + cc;
            float* Vd = sm + (t % 3) * KV_STAGE + 64 * KS_ST + cr * VS_ST + cc;
            const float* kgp = kbase + (size_t)(k0 + cr) * QKV_N + cc;
            const float* vgp = vbase + (size_t)(k0 + cr) * QKV_N + cc;
            #pragma unroll
            for (int j = 0; j < 16; j += 4) {
                cp16(Kd + j, kgp + j);
                cp16(Vd + j, vgp + j);
            }
        }
        asm volatile("cp.async.commit_group;" ::: "memory");
    };

    issue(0);
    issue(1);

    for (int kt = 0; kt < ktmax; ++kt) {
        const int k0 = kt << 6;
        asm volatile("cp.async.wait_group 1;" ::: "memory");
        __syncthreads();            // stage ready + guards Ps/V reuse
        issue(kt + 2);

        const uint32_t* Ku = (const uint32_t*)(sm + (kt % 3) * KV_STAGE);
        const uint32_t* Vu = Ku + 64 * KS_ST;

        // S = Q @ K^T
        float s[8][4];
        #pragma unroll
        for (int nt = 0; nt < 8; nt++)
            #pragma unroll
            for (int j = 0; j < 4; j++) s[nt][j] = 0.0f;

        #pragma unroll
        for (int kc = 0; kc < 8; kc++) {
            const int kb = kc << 3;
            #pragma unroll
            for (int nt = 0; nt < 8; nt++) {
                uint32_t b0 = Ku[(nt * 8 + qr) * KS_ST + kb + qc];
                uint32_t b1 = Ku[(nt * 8 + qr) * KS_ST + kb + qc + 4];
                asm volatile(
                    "mma.sync.aligned.m16n8k8.row.col.f32.tf32.tf32.f32 "
                    "{%0,%1,%2,%3}, {%4,%5,%6,%7}, {%8,%9}, {%0,%1,%2,%3};"
                    : "+f"(s[nt][0]), "+f"(s[nt][1]), "+f"(s[nt][2]), "+f"(s[nt][3])
                    : "r"(qa[kc][0]), "r"(qa[kc][1]), "r"(qa[kc][2]), "r"(qa[kc][3]),
                      "r"(b0), "r"(b1));
            }
        }

        if (k0 + 63 > q0 + wq) {
            const int row0 = q0 + wq + qr;
            #pragma unroll
            for (int nt = 0; nt < 8; nt++) {
                const int col = k0 + nt * 8 + 2 * qc;
                if (col     > row0)     s[nt][0] = -1e30f;
                if (col + 1 > row0)     s[nt][1] = -1e30f;
                if (col     > row0 + 8) s[nt][2] = -1e30f;
                if (col + 1 > row0 + 8) s[nt][3] = -1e30f;
            }
        }

        float rm0 = -1e30f, rm1 = -1e30f;
        #pragma unroll
        for (int nt = 0; nt < 8; nt++) {
            rm0 = fmaxf(rm0, fmaxf(s[nt][0], s[nt][1]));
            rm1 = fmaxf(rm1, fmaxf(s[nt][2], s[nt][3]));
        }
        rm0 = fmaxf(rm0, __shfl_xor_sync(0xffffffffu, rm0, 1));
        rm0 = fmaxf(rm0, __shfl_xor_sync(0xffffffffu, rm0, 2));
        rm1 = fmaxf(rm1, __shfl_xor_sync(0xffffffffu, rm1, 1));
        rm1 = fmaxf(rm1, __shfl_xor_sync(0xffffffffu, rm1, 2));

        const float mn0 = fmaxf(m0v, rm0);
        const float mn1 = fmaxf(m1v, rm1);
        const float al0 = __expf(m0v - mn0);
        const float al1 = __expf(m1v - mn1);
        m0v = mn0; m1v = mn1;

        float rs0 = 0.0f, rs1 = 0.0f;
        #pragma unroll
        for (int nt = 0; nt < 8; nt++) {
            s[nt][0] = __expf(s[nt][0] - mn0);
            s[nt][1] = __expf(s[nt][1] - mn0);
            s[nt][2] = __expf(s[nt][2] - mn1);
            s[nt][3] = __expf(s[nt][3] - mn1);
            rs0 += s[nt][0] + s[nt][1];
            rs1 += s[nt][2] + s[nt][3];
        }
        rs0 += __shfl_xor_sync(0xffffffffu, rs0, 1);
        rs0 += __shfl_xor_sync(0xffffffffu, rs0, 2);
        rs1 += __shfl_xor_sync(0xffffffffu, rs1, 1);
        rs1 += __shfl_xor_sync(0xffffffffu, rs1, 2);
        l0 = l0 * al0 + rs0;
        l1 = l1 * al1 + rs1;

        #pragma unroll
        for (int dt = 0; dt < 8; dt++) {
            o[dt][0] *= al0; o[dt][1] *= al0;
            o[dt][2] *= al1; o[dt][3] *= al1;
        }

        {
            float* p0 = Ps + (wq + qr) * PS_ST;
            float* p1 = p0 + 8 * PS_ST;
            #pragma unroll
            for (int nt = 0; nt < 8; nt++) {
                const int c = (nt * 8 + 2 * qc) ^ swz;
                float2 a, bb;
                a.x  = rtf(s[nt][0]);
                a.y  = rtf(s[nt][1]);
                bb.x = rtf(s[nt][2]);
                bb.y = rtf(s[nt][3]);
                *(float2*)(p0 + c) = a;
                *(float2*)(p1 + c) = bb;
            }
        }
        __syncthreads();

        const uint32_t* Pu = (const uint32_t*)Ps;
        #pragma unroll
        for (int kc = 0; kc < 8; kc++) {
            const int kb = kc << 3;
            uint32_t a0 = Pu[(wq + qr) * PS_ST     + ((kb + qc) ^ swz)];
            uint32_t a1 = Pu[(wq + qr + 8) * PS_ST + ((kb + qc) ^ swz)];
            uint32_t a2 = Pu[(wq + qr) * PS_ST     + ((kb + qc + 4) ^ swz)];
            uint32_t a3 = Pu[(wq + qr + 8) * PS_ST + ((kb + qc + 4) ^ swz)];
            #pragma unroll
            for (int dt = 0; dt < 8; dt++) {
                uint32_t b0 = Vu[(kb + qc) * VS_ST + dt * 8 + qr];
                uint32_t b1 = Vu[(kb + qc + 4) * VS_ST + dt * 8 + qr];
                asm volatile(
                    "mma.sync.aligned.m16n8k8.row.col.f32.tf32.tf32.f32 "
                    "{%0,%1,%2,%3}, {%4,%5,%6,%7}, {%8,%9}, {%0,%1,%2,%3};"
                    : "+f"(o[dt][0]), "+f"(o[dt][1]), "+f"(o[dt][2]), "+f"(o[dt][3])
                    : "r"(a0), "r"(a1), "r"(a2), "r"(a3), "r"(b0), "r"(b1));
            }
        }
    }

    // normalize + write merged-heads output in packed-A layout (for proj GEMM)
    // j(k) = ((k&3)<<1) | ((k>>2)&1);  pairs (2qc, 2qc+1) -> (ja, jb)
    const int ja = (((2 * qc) & 3) << 1) | (((2 * qc) >> 2) & 1);
    const int jb = (((2 * qc + 1) & 3) << 1) | (((2 * qc + 1) >> 2) & 1);
    const float inv0 = 1.0f / l0;
    const float inv1 = 1.0f / l1;
    float* o0 = outp + ((size_t)b * S_LEN + q0 + wq + qr) * DMODEL + h * DH;
    float* o1 = o0 + (size_t)8 * DMODEL;
    #pragma unroll
    for (int dt = 0; dt < 8; dt++) {
        o0[dt * 8 + ja] = rtf(o[dt][0] * inv0);
        o0[dt * 8 + jb] = rtf(o[dt][1] * inv0);
        o1[dt * 8 + ja] = rtf(o[dt][2] * inv1);
        o1[dt * 8 + jb] = rtf(o[dt][3] * inv1);
    }
}

// ---------------------------------------------------------------------------
// Launch
// ---------------------------------------------------------------------------
extern "C" void kernel_launch(void* const* d_in, const int* in_sizes, int n_in,
                              void* d_out, int out_size)
{
    const float* hidden = (const float*)d_in[0];
    const float* w_attn = (const float*)d_in[1];
    const float* b_attn = (const float*)d_in[2];
    const float* w_proj = (const float*)d_in[3];
    const float* b_proj = (const float*)d_in[4];
    float* out = (float*)d_out;

    float *qkv, *attn, *hidp, *wqp, *wpp;
    cudaGetSymbolAddress((void**)&qkv,  g_qkv);
    cudaGetSymbolAddress((void**)&attn, g_attn);
    cudaGetSymbolAddress((void**)&hidp, g_hid_p);
    cudaGetSymbolAddress((void**)&wqp,  g_wqkv_p);
    cudaGetSymbolAddress((void**)&wpp,  g_wproj_p);

    // 0) pack + tf32-round GEMM operands
    pack_a_kernel<<<(NT * KDIM) / 1024, 256>>>(hidden, hidp, KDIM);
    pack_b_kernel<<<(KDIM * QKV_N) / 1024, 256>>>(w_attn, wqp, QKV_N);
    pack_b_kernel<<<(KDIM * DMODEL) / 1024, 256>>>(w_proj, wpp, DMODEL);

    const size_t gsm = (size_t)STAGES * STAGE_FLOATS * sizeof(float); // 110592
    cudaFuncSetAttribute(tf32_mma_gemm,
                         cudaFuncAttributeMaxDynamicSharedMemorySize, (int)gsm);

    // 1) QKV projection (epilogue tf32-rounds for attention)
    tf32_mma_gemm<<<dim3(QKV_N / 128, NT / 128), 256, gsm>>>(
        hidp, wqp, b_attn, qkv, NT, QKV_N, KDIM, 1);

    // 2) causal flash attention (tensor cores, pipelined K/V)
    {
        const size_t fsm = (size_t)FA_SMEM_FLOATS * sizeof(float); // 144384
        cudaFuncSetAttribute(flash_attn_tc,
                             cudaFuncAttributeMaxDynamicSharedMemorySize, (int)fsm);
        dim3 grid(S_LEN / 128, NH, BATCH);
        flash_attn_tc<<<grid, 256, fsm>>>(qkv, attn);
    }

    // 3) output projection (plain fp32 output)
    tf32_mma_gemm<<<dim3(DMODEL / 128, NT / 128), 256, gsm>>>(
        attn, wpp, b_proj, out, NT, DMODEL, KDIM, 0);
}

// round 7
// speedup vs baseline: 6.8265x; 2.1243x over previous
#include <cuda_runtime.h>
#include <cuda_fp16.h>
#include <cstdint>
#include <cstddef>

// Problem constants
#define BATCH   4
#define S_LEN   2048
#define DMODEL  1024
#define NH      16
#define DH      64
#define NT      (BATCH * S_LEN)     // 8192 rows
#define QKV_N   (3 * DMODEL)        // 3072
#define KDIM    1024

// Scratch (device globals: allocation-free)
__device__ __half g_qkv[(size_t)NT * QKV_N];     // fp16, natural, Q pre-scaled x0.125
__device__ __half g_attn[(size_t)NT * DMODEL];   // fp16, natural
__device__ __half g_hid_h[(size_t)NT * KDIM];
__device__ __half g_wqkv_h[(size_t)KDIM * QKV_N];
__device__ __half g_wproj_h[(size_t)KDIM * DMODEL];

__device__ __forceinline__ void cp16(void* smem_dst, const void* gsrc) {
    uint32_t s = (uint32_t)__cvta_generic_to_shared(smem_dst);
    asm volatile("cp.async.cg.shared.global [%0], [%1], 16;"
                 :: "r"(s), "l"(gsrc) : "memory");
}
__device__ __forceinline__ uint32_t h2u(float a, float b) {
    __half2 h = __floats2half2_rn(a, b);
    return *(uint32_t*)&h;
}
#define LDSM_X4(r0, r1, r2, r3, addr)                                        \
    asm volatile("ldmatrix.sync.aligned.m8n8.x4.shared.b16 {%0,%1,%2,%3}, [%4];" \
                 : "=r"(r0), "=r"(r1), "=r"(r2), "=r"(r3) : "r"(addr))
#define LDSM_X4T(r0, r1, r2, r3, addr)                                       \
    asm volatile("ldmatrix.sync.aligned.m8n8.x4.trans.shared.b16 {%0,%1,%2,%3}, [%4];" \
                 : "=r"(r0), "=r"(r1), "=r"(r2), "=r"(r3) : "r"(addr))
#define MMA16816(c, a0, a1, a2, a3, b0, b1)                                  \
    asm volatile("mma.sync.aligned.m16n8k16.row.col.f32.f16.f16.f32 "        \
                 "{%0,%1,%2,%3}, {%4,%5,%6,%7}, {%8,%9}, {%0,%1,%2,%3};"     \
                 : "+f"((c)[0]), "+f"((c)[1]), "+f"((c)[2]), "+f"((c)[3])    \
                 : "r"(a0), "r"(a1), "r"(a2), "r"(a3), "r"(b0), "r"(b1))

// ---------------------------------------------------------------------------
// Prep: fp32 -> fp16 (rn), vectorized
// ---------------------------------------------------------------------------
__global__ __launch_bounds__(256) void f2h_kernel(
    const float* __restrict__ in, __half* __restrict__ out, int n4)
{
    int i = blockIdx.x * blockDim.x + threadIdx.x;
    if (i < n4) {
        float4 v = ((const float4*)in)[i];
        uint2 o;
        o.x = h2u(v.x, v.y);
        o.y = h2u(v.z, v.w);
        ((uint2*)out)[i] = o;
    }
}

// ---------------------------------------------------------------------------
// fp16 mma.sync GEMM with fp32 bias: C = A @ B + bias.
// A fp16 [M][K] natural, B fp16 [K][N] natural. CTA 128x128, K-tile 32,
// 256 threads (8 warps @ 32x64), cp.async 3 stages, 2 CTAs/SM.
// Fragments via ldmatrix (A non-trans, B trans), conflict-free strides.
// Output: Ch!=null -> fp16 (scale_q: cols < DMODEL scaled by 0.125);
//         else fp32 to Cf.
// ---------------------------------------------------------------------------
#define GA_RB 80                      // A smem row bytes (40 fp16)
#define GB_RB 272                     // B smem row bytes (136 fp16)
#define G_ABYTES (128 * GA_RB)        // 10240
#define G_BBYTES (32 * GB_RB)         // 8704
#define G_STAGE  (G_ABYTES + G_BBYTES)// 18944
#define STAGES 3

__global__ __launch_bounds__(256, 2) void h16_mma_gemm(
    const __half* __restrict__ A, const __half* __restrict__ B,
    const float* __restrict__ bias, float* __restrict__ Cf,
    __half* __restrict__ Ch, int M, int N, int K, int scale_q)
{
    extern __shared__ char smem[];

    const int tid  = threadIdx.x;
    const int wid  = tid >> 5;
    const int lane = tid & 31;
    const int qr   = lane >> 2;
    const int qc   = lane & 3;

    const int m0 = blockIdx.y << 7;
    const int n0 = blockIdx.x << 7;
    const int wm = (wid & 3) << 5;
    const int wn = (wid >> 2) << 6;

    // cp.async mappings
    const int ar = tid >> 1;              // A row 0..127
    const int ac = (tid & 1) << 1;        // A chunk base (0 or 2), 16B chunks

    float acc[2][8][4];
    #pragma unroll
    for (int mt = 0; mt < 2; mt++)
        #pragma unroll
        for (int nt = 0; nt < 8; nt++)
            #pragma unroll
            for (int j = 0; j < 4; j++) acc[mt][nt][j] = 0.0f;

    const int KT = K >> 5;

    auto issue = [&](int t) {
        if (t < KT) {
            const int k0 = t << 5;
            char* base = smem + (t % STAGES) * G_STAGE;
            const char* asrc = (const char*)A + ((size_t)(m0 + ar) * K + k0) * 2;
            cp16(base + ar * GA_RB + ac * 16,      asrc + ac * 16);
            cp16(base + ar * GA_RB + ac * 16 + 16, asrc + ac * 16 + 16);
            #pragma unroll
            for (int i = 0; i < 2; i++) {
                const int id = tid + (i << 8);
                const int row = id >> 4, ch = id & 15;
                cp16(base + G_ABYTES + row * GB_RB + ch * 16,
                     (const char*)B + ((size_t)(k0 + row) * N + n0) * 2 + ch * 16);
            }
        }
        asm volatile("cp.async.commit_group;" ::: "memory");
    };

    auto compute = [&](int si) {
        const uint32_t sa = (uint32_t)__cvta_generic_to_shared(smem + si * G_STAGE);
        const uint32_t sb = sa + G_ABYTES;
        #pragma unroll
        for (int ks = 0; ks < 2; ks++) {
            uint32_t a[2][4], b[8][2];
            #pragma unroll
            for (int mt = 0; mt < 2; mt++) {
                uint32_t ad = sa + (wm + (mt << 4) + (lane & 15)) * GA_RB
                            + (ks * 16 + ((lane >> 4) << 3)) * 2;
                LDSM_X4(a[mt][0], a[mt][1], a[mt][2], a[mt][3], ad);
            }
            #pragma unroll
            for (int ntp = 0; ntp < 4; ntp++) {
                uint32_t bd = sb + (ks * 16 + (lane & 15)) * GB_RB
                            + (wn + ntp * 16 + ((lane >> 4) << 3)) * 2;
                LDSM_X4T(b[2 * ntp][0], b[2 * ntp][1],
                         b[2 * ntp + 1][0], b[2 * ntp + 1][1], bd);
            }
            #pragma unroll
            for (int mt = 0; mt < 2; mt++)
                #pragma unroll
                for (int nt = 0; nt < 8; nt++)
                    MMA16816(acc[mt][nt], a[mt][0], a[mt][1], a[mt][2], a[mt][3],
                             b[nt][0], b[nt][1]);
        }
    };

    issue(0);
    issue(1);

    for (int t = 0; t < KT; ++t) {
        asm volatile("cp.async.wait_group 1;" ::: "memory");
        __syncthreads();
        issue(t + 2);
        compute(t % STAGES);
    }

    #pragma unroll
    for (int mt = 0; mt < 2; mt++) {
        const int row = m0 + wm + (mt << 4) + qr;
        #pragma unroll
        for (int nt = 0; nt < 8; nt++) {
            const int col = n0 + wn + (nt << 3) + (qc << 1);
            const float2 bv = *(const float2*)(bias + col);
            float x0 = acc[mt][nt][0] + bv.x, y0 = acc[mt][nt][1] + bv.y;
            float x1 = acc[mt][nt][2] + bv.x, y1 = acc[mt][nt][3] + bv.y;
            if (Ch) {
                const float sc = (scale_q && col < DMODEL) ? 0.125f : 1.0f;
                *(uint32_t*)(Ch + (size_t)row * N + col)       = h2u(x0 * sc, y0 * sc);
                *(uint32_t*)(Ch + (size_t)(row + 8) * N + col) = h2u(x1 * sc, y1 * sc);
            } else {
                *(float2*)(Cf + (size_t)row * N + col)       = make_float2(x0, y0);
                *(float2*)(Cf + (size_t)(row + 8) * N + col) = make_float2(x1, y1);
            }
        }
    }
}

// ---------------------------------------------------------------------------
// fp16 tensor-core flash attention (causal). CTA: 128 q-rows x 64 keys/iter.
// Q frags direct from global (pre-scaled). K/V raw fp16 cp.async, 3 stages.
// P stays in registers (S C-frags -> A-frags). Output fp16 natural.
// ---------------------------------------------------------------------------
#define KV_RB 144                       // 72 fp16 per row
#define KV_HALF (64 * KV_RB)            // 9216 (K region; V follows)
#define KV_STAGE (2 * KV_HALF)          // 18432
#define FA_SMEM (3 * KV_STAGE)          // 55296

__global__ __launch_bounds__(256) void flash_attn_h16(
    const __half* __restrict__ qkv, __half* __restrict__ outp)
{
    extern __shared__ char smem[];

    const int qt = blockIdx.x;
    const int h  = blockIdx.y;
    const int b  = blockIdx.z;

    const int tid  = threadIdx.x;
    const int wid  = tid >> 5;
    const int lane = tid & 31;
    const int qr   = lane >> 2;
    const int qc   = lane & 3;
    const int wq   = wid << 4;
    const int q0   = qt << 7;

    const __half* qb = qkv + (size_t)b * S_LEN * QKV_N + h * DH;
    const __half* kb = qb + DMODEL;
    const __half* vb = qb + 2 * DMODEL;

    // Persistent Q fragments (already scaled by 0.125 in QKV epilogue)
    uint32_t qa[4][4];
    {
        const int r0 = q0 + wq + qr;
        const __half* p0 = qb + (size_t)r0 * QKV_N;
        const __half* p1 = p0 + (size_t)8 * QKV_N;
        #pragma unroll
        for (int ks = 0; ks < 4; ks++) {
            qa[ks][0] = *(const uint32_t*)(p0 + ks * 16 + 2 * qc);
            qa[ks][1] = *(const uint32_t*)(p1 + ks * 16 + 2 * qc);
            qa[ks][2] = *(const uint32_t*)(p0 + ks * 16 + 2 * qc + 8);
            qa[ks][3] = *(const uint32_t*)(p1 + ks * 16 + 2 * qc + 8);
        }
    }

    float o[8][4];
    #pragma unroll
    for (int dt = 0; dt < 8; dt++)
        #pragma unroll
        for (int j = 0; j < 4; j++) o[dt][j] = 0.0f;
    float m0v = -1e30f, m1v = -1e30f, l0 = 0.0f, l1 = 0.0f;

    const int ktmax = 2 * qt + 2;

    auto issue = [&](int t) {
        if (t < ktmax) {
            const int k0 = t << 6;
            char* base = smem + (t % 3) * KV_STAGE;
            #pragma unroll
            for (int i = 0; i < 2; i++) {
                const int id = tid + (i << 8);
                const int row = id >> 3, ch = id & 7;
                const size_t gof = ((size_t)(k0 + row) * QKV_N) * 2 + ch * 16;
                cp16(base + row * KV_RB + ch * 16, (const char*)kb + gof);
                cp16(base + KV_HALF + row * KV_RB + ch * 16, (const char*)vb + gof);
            }
        }
        asm volatile("cp.async.commit_group;" ::: "memory");
    };

    issue(0);
    issue(1);

    for (int kt = 0; kt < ktmax; ++kt) {
        const int k0 = kt << 6;
        asm volatile("cp.async.wait_group 1;" ::: "memory");
        __syncthreads();
        issue(kt + 2);

        const uint32_t sk = (uint32_t)__cvta_generic_to_shared(smem + (kt % 3) * KV_STAGE);
        const uint32_t sv = sk + KV_HALF;

        // S = Q @ K^T
        float s[8][4];
        #pragma unroll
        for (int nt = 0; nt < 8; nt++)
            #pragma unroll
            for (int j = 0; j < 4; j++) s[nt][j] = 0.0f;

        #pragma unroll
        for (int ks2 = 0; ks2 < 2; ks2++) {
            #pragma unroll
            for (int nt = 0; nt < 8; nt++) {
                uint32_t r0, r1, r2, r3;
                uint32_t ad = sk + (nt * 8 + (lane & 7)) * KV_RB
                            + (ks2 * 32 + ((lane >> 3) << 3)) * 2;
                LDSM_X4(r0, r1, r2, r3, ad);
                MMA16816(s[nt], qa[2 * ks2][0], qa[2 * ks2][1],
                         qa[2 * ks2][2], qa[2 * ks2][3], r0, r1);
                MMA16816(s[nt], qa[2 * ks2 + 1][0], qa[2 * ks2 + 1][1],
                         qa[2 * ks2 + 1][2], qa[2 * ks2 + 1][3], r2, r3);
            }
        }

        // causal mask
        if (k0 + 63 > q0 + wq) {
            const int row0 = q0 + wq + qr;
            #pragma unroll
            for (int nt = 0; nt < 8; nt++) {
                const int col = k0 + nt * 8 + 2 * qc;
                if (col     > row0)     s[nt][0] = -1e30f;
                if (col + 1 > row0)     s[nt][1] = -1e30f;
                if (col     > row0 + 8) s[nt][2] = -1e30f;
                if (col + 1 > row0 + 8) s[nt][3] = -1e30f;
            }
        }

        // online softmax
        float rm0 = -1e30f, rm1 = -1e30f;
        #pragma unroll
        for (int nt = 0; nt < 8; nt++) {
            rm0 = fmaxf(rm0, fmaxf(s[nt][0], s[nt][1]));
            rm1 = fmaxf(rm1, fmaxf(s[nt][2], s[nt][3]));
        }
        rm0 = fmaxf(rm0, __shfl_xor_sync(0xffffffffu, rm0, 1));
        rm0 = fmaxf(rm0, __shfl_xor_sync(0xffffffffu, rm0, 2));
        rm1 = fmaxf(rm1, __shfl_xor_sync(0xffffffffu, rm1, 1));
        rm1 = fmaxf(rm1, __shfl_xor_sync(0xffffffffu, rm1, 2));

        const float mn0 = fmaxf(m0v, rm0);
        const float mn1 = fmaxf(m1v, rm1);
        const float al0 = __expf(m0v - mn0);
        const float al1 = __expf(m1v - mn1);
        m0v = mn0; m1v = mn1;

        float rs0 = 0.0f, rs1 = 0.0f;
        #pragma unroll
        for (int nt = 0; nt < 8; nt++) {
            s[nt][0] = __expf(s[nt][0] - mn0);
            s[nt][1] = __expf(s[nt][1] - mn0);
            s[nt][2] = __expf(s[nt][2] - mn1);
            s[nt][3] = __expf(s[nt][3] - mn1);
            rs0 += s[nt][0] + s[nt][1];
            rs1 += s[nt][2] + s[nt][3];
        }
        rs0 += __shfl_xor_sync(0xffffffffu, rs0, 1);
        rs0 += __shfl_xor_sync(0xffffffffu, rs0, 2);
        rs1 += __shfl_xor_sync(0xffffffffu, rs1, 1);
        rs1 += __shfl_xor_sync(0xffffffffu, rs1, 2);
        l0 = l0 * al0 + rs0;
        l1 = l1 * al1 + rs1;

        #pragma unroll
        for (int dt = 0; dt < 8; dt++) {
            o[dt][0] *= al0; o[dt][1] *= al0;
            o[dt][2] *= al1; o[dt][3] *= al1;
        }

        // O += P @ V  (P directly from s-regs as A-frags)
        #pragma unroll
        for (int ks = 0; ks < 4; ks++) {
            const uint32_t pa0 = h2u(s[2 * ks][0], s[2 * ks][1]);
            const uint32_t pa1 = h2u(s[2 * ks][2], s[2 * ks][3]);
            const uint32_t pa2 = h2u(s[2 * ks + 1][0], s[2 * ks + 1][1]);
            const uint32_t pa3 = h2u(s[2 * ks + 1][2], s[2 * ks + 1][3]);
            #pragma unroll
            for (int dtp = 0; dtp < 4; dtp++) {
                uint32_t r0, r1, r2, r3;
                uint32_t ad = sv + (ks * 16 + (lane & 15)) * KV_RB
                            + (dtp * 16 + ((lane >> 4) << 3)) * 2;
                LDSM_X4T(r0, r1, r2, r3, ad);
                MMA16816(o[2 * dtp],     pa0, pa1, pa2, pa3, r0, r1);
                MMA16816(o[2 * dtp + 1], pa0, pa1, pa2, pa3, r2, r3);
            }
        }
    }

    // normalize + write merged-heads output (fp16 natural)
    const float inv0 = 1.0f / l0;
    const float inv1 = 1.0f / l1;
    const int r0 = q0 + wq + qr;
    __half* po0 = outp + ((size_t)b * S_LEN + r0) * DMODEL + h * DH + 2 * qc;
    __half* po1 = po0 + (size_t)8 * DMODEL;
    #pragma unroll
    for (int dt = 0; dt < 8; dt++) {
        *(uint32_t*)(po0 + dt * 8) = h2u(o[dt][0] * inv0, o[dt][1] * inv0);
        *(uint32_t*)(po1 + dt * 8) = h2u(o[dt][2] * inv1, o[dt][3] * inv1);
    }
}

// ---------------------------------------------------------------------------
// Launch
// ---------------------------------------------------------------------------
extern "C" void kernel_launch(void* const* d_in, const int* in_sizes, int n_in,
                              void* d_out, int out_size)
{
    const float* hidden = (const float*)d_in[0];
    const float* w_attn = (const float*)d_in[1];
    const float* b_attn = (const float*)d_in[2];
    const float* w_proj = (const float*)d_in[3];
    const float* b_proj = (const float*)d_in[4];
    float* out = (float*)d_out;

    __half *qkv, *attn, *hidh, *wqh, *wph;
    cudaGetSymbolAddress((void**)&qkv,  g_qkv);
    cudaGetSymbolAddress((void**)&attn, g_attn);
    cudaGetSymbolAddress((void**)&hidh, g_hid_h);
    cudaGetSymbolAddress((void**)&wqh,  g_wqkv_h);
    cudaGetSymbolAddress((void**)&wph,  g_wproj_h);

    // 0) fp32 -> fp16 conversions
    {
        int n4 = (NT * KDIM) / 4;
        f2h_kernel<<<(n4 + 255) / 256, 256>>>(hidden, hidh, n4);
        n4 = (KDIM * QKV_N) / 4;
        f2h_kernel<<<(n4 + 255) / 256, 256>>>(w_attn, wqh, n4);
        n4 = (KDIM * DMODEL) / 4;
        f2h_kernel<<<(n4 + 255) / 256, 256>>>(w_proj, wph, n4);
    }

    const size_t gsm = (size_t)STAGES * G_STAGE;   // 56832
    cudaFuncSetAttribute(h16_mma_gemm,
                         cudaFuncAttributeMaxDynamicSharedMemorySize, (int)gsm);

    // 1) QKV projection -> fp16 qkv (Q scaled by 0.125)
    h16_mma_gemm<<<dim3(QKV_N / 128, NT / 128), 256, gsm>>>(
        hidh, wqh, b_attn, nullptr, qkv, NT, QKV_N, KDIM, 1);

    // 2) causal flash attention
    {
        cudaFuncSetAttribute(flash_attn_h16,
                             cudaFuncAttributeMaxDynamicSharedMemorySize, FA_SMEM);
        dim3 grid(S_LEN / 128, NH, BATCH);
        flash_attn_h16<<<grid, 256, FA_SMEM>>>(qkv, attn);
    }

    // 3) output projection -> fp32 out
    h16_mma_gemm<<<dim3(DMODEL / 128, NT / 128), 256, gsm>>>(
        attn, wph, b_proj, out, nullptr, NT, DMODEL, KDIM, 0);
}